// round 2
// baseline (speedup 1.0000x reference)
#include <cuda_runtime.h>
#include <cuda_bf16.h>
#include <cstdint>

// ---------------- problem dims ----------------
#define CC   2048
#define KTT  64
#define DD   1024
#define DE   128
#define DF   256
#define NH   8
#define DHH  128
#define DX   1152   // D + De
#define PHH  1024
#define MKV  (CC*KTT)        // 131072
#define NKV  2048            // K cols then V cols

// ---------------- scratch (__device__ globals; no allocations) ----------------
__device__ __align__(128) __nv_bfloat16 g_Fp[(size_t)MKV * DX];     // 302 MB
__device__ __align__(128) __nv_bfloat16 g_KV[(size_t)MKV * NKV];    // 536 MB
__device__ __align__(128) __nv_bfloat16 g_Wkv[NKV * DX];
__device__ __align__(128) __nv_bfloat16 g_W2b[DD * DD];
__device__ __align__(128) __nv_bfloat16 g_Wfb[DD * DF];
__device__ __align__(128) __nv_bfloat16 g_g1wb[PHH * DX];
__device__ __align__(128) __nv_bfloat16 g_g2wb[DD * PHH];
__device__ __align__(128) __nv_bfloat16 g_wb[CC * DD];
__device__ __align__(128) __nv_bfloat16 g_fCb[CC * DF];
__device__ __align__(128) __nv_bfloat16 g_ginb[CC * DX];
__device__ __align__(128) __nv_bfloat16 g_hmid[CC * PHH];
__device__ __align__(128) float g_fCp[CC * DD];
__device__ __align__(128) float g_Q[CC * DD];
__device__ __align__(128) float g_g[CC * DD];

// ---------------- PTX helpers ----------------
__device__ __forceinline__ void cpasync16(void* dst, const void* src) {
    uint32_t d = (uint32_t)__cvta_generic_to_shared(dst);
    asm volatile("cp.async.cg.shared.global [%0], [%1], 16;\n" :: "r"(d), "l"(src));
}
__device__ __forceinline__ void cp_commit() {
    asm volatile("cp.async.commit_group;\n" ::: "memory");
}
template <int N>
__device__ __forceinline__ void cp_wait() {
    asm volatile("cp.async.wait_group %0;\n" :: "n"(N) : "memory");
}
__device__ __forceinline__ void ldm_x4(uint32_t* r, const void* p) {
    uint32_t a = (uint32_t)__cvta_generic_to_shared(p);
    asm volatile("ldmatrix.sync.aligned.m8n8.x4.shared.b16 {%0,%1,%2,%3}, [%4];\n"
                 : "=r"(r[0]), "=r"(r[1]), "=r"(r[2]), "=r"(r[3]) : "r"(a));
}
__device__ __forceinline__ void mma16816(float* c, const uint32_t* a, uint32_t b0, uint32_t b1) {
    asm volatile(
        "mma.sync.aligned.m16n8k16.row.col.f32.bf16.bf16.f32 "
        "{%0,%1,%2,%3},{%4,%5,%6,%7},{%8,%9},{%0,%1,%2,%3};\n"
        : "+f"(c[0]), "+f"(c[1]), "+f"(c[2]), "+f"(c[3])
        : "r"(a[0]), "r"(a[1]), "r"(a[2]), "r"(a[3]), "r"(b0), "r"(b1));
}

// ---------------- prep kernels ----------------
// Fp = bf16(concat(F, Et)) along last dim, vectorized float4 -> bf16x4
__global__ void prep_fp_k(const float* __restrict__ F, const float* __restrict__ Et,
                          __nv_bfloat16* __restrict__ Fp) {
    const int n4 = MKV * DX / 4;
    int i = blockIdx.x * blockDim.x + threadIdx.x;
    if (i >= n4) return;
    int ck = i / 288;                 // 1152/4 float4s per row
    int x4 = (i - ck * 288) * 4;
    float4 f;
    if (x4 < DD) f = ((const float4*)F)[(size_t)ck * 256 + (x4 >> 2)];
    else         f = ((const float4*)Et)[(size_t)ck * 32 + ((x4 - DD) >> 2)];
    __nv_bfloat162* d = (__nv_bfloat162*)(Fp + (size_t)ck * DX + x4);
    d[0] = __floats2bfloat162_rn(f.x, f.y);
    d[1] = __floats2bfloat162_rn(f.z, f.w);
}

// generic f32 -> bf16 convert (n4 = count/4)
__global__ void cvt_k(const float* __restrict__ s, __nv_bfloat16* __restrict__ d, int n4) {
    int i = blockIdx.x * blockDim.x + threadIdx.x;
    if (i >= n4) return;
    float4 f = ((const float4*)s)[i];
    __nv_bfloat162* o = (__nv_bfloat162*)(d + (size_t)i * 4);
    o[0] = __floats2bfloat162_rn(f.x, f.y);
    o[1] = __floats2bfloat162_rn(f.z, f.w);
}

// gin = bf16(concat(w, mean_kt(Et)))
__global__ void prep_gin_k(const float* __restrict__ w, const float* __restrict__ Et,
                           __nv_bfloat16* __restrict__ gin) {
    int i = blockIdx.x * blockDim.x + threadIdx.x;
    if (i >= CC * DX) return;
    int c = i / DX, x = i - c * DX;
    float v;
    if (x < DD) {
        v = w[(size_t)c * DD + x];
    } else {
        int j = x - DD;
        const float* p = Et + (size_t)c * KTT * DE + j;
        float s = 0.f;
        #pragma unroll 8
        for (int kt = 0; kt < KTT; kt++) s += p[(size_t)kt * DE];
        v = s * (1.0f / 64.0f);
    }
    gin[i] = __float2bfloat16(v);
}

// ---------------- GEMM: C[M,N] = A[M,K] @ B[N,K]^T  (bf16 in, fp32 accum) ----------------
enum { M_PLAIN = 0, M_ADDB = 1, M_RELU = 2, M_SIG = 3, M_KV = 4 };

template <int MODE>
__global__ void __launch_bounds__(256)
gemm_k(const __nv_bfloat16* __restrict__ A, const __nv_bfloat16* __restrict__ B,
       void* __restrict__ Out, int M, int N, int K,
       const float* __restrict__ extra, const float* __restrict__ scal) {
    __shared__ __align__(16) __nv_bfloat16 sA[2][128][40];   // BK=32, pad 8 halves
    __shared__ __align__(16) __nv_bfloat16 sB[2][128][40];

    const int tid  = threadIdx.x;
    const int lane = tid & 31, warp = tid >> 5;
    const int wm = (warp >> 1) << 5;     // warp tile 32(m) x 64(n), 4x2 warp grid
    const int wn = (warp & 1) << 6;
    const int m0 = blockIdx.y << 7, n0 = blockIdx.x << 7;

    float acc[2][8][4];
    #pragma unroll
    for (int i = 0; i < 2; i++)
        #pragma unroll
        for (int j = 0; j < 8; j++)
            #pragma unroll
            for (int r = 0; r < 4; r++) acc[i][j][r] = 0.f;

    auto tile_load = [&](int buf, int kt) {
        #pragma unroll
        for (int r = 0; r < 2; r++) {
            int id  = tid + (r << 8);
            int row = id >> 2;
            int cc  = (id & 3) << 3;
            cpasync16(&sA[buf][row][cc], A + (size_t)(m0 + row) * K + kt + cc);
            cpasync16(&sB[buf][row][cc], B + (size_t)(n0 + row) * K + kt + cc);
        }
    };

    tile_load(0, 0);
    cp_commit();
    const int nk = K >> 5;
    for (int t = 0; t < nk; t++) {
        if (t + 1 < nk) {
            tile_load((t + 1) & 1, (t + 1) << 5);
            cp_commit();
            cp_wait<1>();
        } else {
            cp_wait<0>();
        }
        __syncthreads();
        const int buf = t & 1;
        #pragma unroll
        for (int s = 0; s < 2; s++) {
            uint32_t af[2][4], bfr[4][4];
            #pragma unroll
            for (int i = 0; i < 2; i++)
                ldm_x4(af[i], &sA[buf][wm + (i << 4) + (lane & 15)][(s << 4) + ((lane >> 4) << 3)]);
            #pragma unroll
            for (int j = 0; j < 4; j++)
                ldm_x4(bfr[j], &sB[buf][wn + (j << 4) + (lane & 15)][(s << 4) + ((lane >> 4) << 3)]);
            #pragma unroll
            for (int i = 0; i < 2; i++)
                #pragma unroll
                for (int j = 0; j < 4; j++) {
                    mma16816(acc[i][2 * j],     af[i], bfr[j][0], bfr[j][2]);
                    mma16816(acc[i][2 * j + 1], af[i], bfr[j][1], bfr[j][3]);
                }
        }
        __syncthreads();
    }

    // epilogue
    float sc = 0.f;
    if (MODE == M_ADDB || MODE == M_KV) sc = scal[0];
    #pragma unroll
    for (int i = 0; i < 2; i++) {
        #pragma unroll
        for (int j = 0; j < 8; j++) {
            const int colg = n0 + wn + (j << 3) + ((lane & 3) << 1);
            #pragma unroll
            for (int r2 = 0; r2 < 2; r2++) {
                const int row = m0 + wm + (i << 4) + (lane >> 2) + (r2 << 3);
                float v0 = acc[i][j][r2 * 2], v1 = acc[i][j][r2 * 2 + 1];
                if (MODE == M_KV) {
                    if (colg < 1024) {   // K half gets + alpha * fCp[c]
                        const float* fp = extra + (size_t)(row >> 6) * DD + colg;
                        v0 += sc * fp[0]; v1 += sc * fp[1];
                    }
                    __nv_bfloat162* o = (__nv_bfloat162*)((__nv_bfloat16*)Out + (size_t)row * N + colg);
                    *o = __floats2bfloat162_rn(v0, v1);
                } else if (MODE == M_PLAIN) {
                    float2* o = (float2*)((float*)Out + (size_t)row * N + colg);
                    *o = make_float2(v0, v1);
                } else if (MODE == M_ADDB) {
                    const float* fp = extra + (size_t)row * N + colg;
                    float2* o = (float2*)((float*)Out + (size_t)row * N + colg);
                    *o = make_float2(v0 + sc * fp[0], v1 + sc * fp[1]);
                } else if (MODE == M_RELU) {
                    v0 = fmaxf(v0 + extra[colg], 0.f);
                    v1 = fmaxf(v1 + extra[colg + 1], 0.f);
                    __nv_bfloat162* o = (__nv_bfloat162*)((__nv_bfloat16*)Out + (size_t)row * N + colg);
                    *o = __floats2bfloat162_rn(v0, v1);
                } else { // M_SIG
                    v0 = 1.f / (1.f + __expf(-(v0 + extra[colg])));
                    v1 = 1.f / (1.f + __expf(-(v1 + extra[colg + 1])));
                    float2* o = (float2*)((float*)Out + (size_t)row * N + colg);
                    *o = make_float2(v0, v1);
                }
            }
        }
    }
}

// ---------------- attention + gate + normalize (1 block per c, 1 warp per head) ----------------
__global__ void __launch_bounds__(256)
attn_k(const __nv_bfloat16* __restrict__ KVp, const float* __restrict__ Q,
       const float* __restrict__ gg, const float* __restrict__ w,
       float* __restrict__ out) {
    const int c = blockIdx.x;
    const int warp = threadIdx.x >> 5, lane = threadIdx.x & 31;
    __shared__ float s_attn[8][64];
    __shared__ float s_sum[8];
    const size_t base = (size_t)c * KTT * NKV;
    const int hoff = warp * DHH;

    float q[4];
    #pragma unroll
    for (int i = 0; i < 4; i++) q[i] = Q[(size_t)c * DD + hoff + (i << 5) + lane];

    for (int kt = 0; kt < KTT; kt++) {
        const __nv_bfloat16* kp = KVp + base + (size_t)kt * NKV + hoff;
        float s = 0.f;
        #pragma unroll
        for (int i = 0; i < 4; i++) s += q[i] * __bfloat162float(kp[(i << 5) + lane]);
        #pragma unroll
        for (int o = 16; o; o >>= 1) s += __shfl_xor_sync(0xffffffffu, s, o);
        if (lane == 0) s_attn[warp][kt] = s * 0.08838834764831845f;  // 1/sqrt(128)
    }
    __syncwarp();
    float v0 = s_attn[warp][lane], v1 = s_attn[warp][lane + 32];
    float mx = fmaxf(v0, v1);
    #pragma unroll
    for (int o = 16; o; o >>= 1) mx = fmaxf(mx, __shfl_xor_sync(0xffffffffu, mx, o));
    float e0 = __expf(v0 - mx), e1 = __expf(v1 - mx);
    float ssum = e0 + e1;
    #pragma unroll
    for (int o = 16; o; o >>= 1) ssum += __shfl_xor_sync(0xffffffffu, ssum, o);
    float inv = 1.f / ssum;
    s_attn[warp][lane]      = e0 * inv;
    s_attn[warp][lane + 32] = e1 * inv;
    __syncwarp();

    float a[4] = {0.f, 0.f, 0.f, 0.f};
    for (int kt = 0; kt < KTT; kt++) {
        float p = s_attn[warp][kt];
        const __nv_bfloat16* vp = KVp + base + (size_t)kt * NKV + 1024 + hoff;
        #pragma unroll
        for (int i = 0; i < 4; i++) a[i] += p * __bfloat162float(vp[(i << 5) + lane]);
    }

    float u[4]; float ss = 0.f;
    #pragma unroll
    for (int i = 0; i < 4; i++) {
        size_t idx = (size_t)c * DD + hoff + (i << 5) + lane;
        u[i] = w[idx] + gg[idx] * a[i];
        ss += u[i] * u[i];
    }
    #pragma unroll
    for (int o = 16; o; o >>= 1) ss += __shfl_xor_sync(0xffffffffu, ss, o);
    if (lane == 0) s_sum[warp] = ss;
    __syncthreads();
    float tot = 0.f;
    #pragma unroll
    for (int h = 0; h < 8; h++) tot += s_sum[h];
    float invn = 1.f / fmaxf(sqrtf(tot), 1e-12f);
    #pragma unroll
    for (int i = 0; i < 4; i++)
        out[(size_t)c * DD + hoff + (i << 5) + lane] = u[i] * invn;
}

// ---------------- launch ----------------
extern "C" void kernel_launch(void* const* d_in, const int* in_sizes, int n_in,
                              void* d_out, int out_size) {
    const float* w   = (const float*)d_in[0];
    const float* F   = (const float*)d_in[1];
    const float* Et  = (const float*)d_in[2];
    const float* fC  = (const float*)d_in[3];
    const float* W1  = (const float*)d_in[4];
    const float* W2  = (const float*)d_in[5];
    const float* Wv  = (const float*)d_in[6];
    const float* Wf  = (const float*)d_in[7];
    const float* alpha = (const float*)d_in[8];
    const float* beta  = (const float*)d_in[9];
    const float* g1w = (const float*)d_in[10];
    const float* g1b = (const float*)d_in[11];
    const float* g2w = (const float*)d_in[12];
    const float* g2b = (const float*)d_in[13];
    float* out = (float*)d_out;

    __nv_bfloat16 *Fp, *KV, *Wkv, *W2b, *Wfb, *g1wb, *g2wb, *wb, *fCb, *gin, *hmid;
    float *fCp, *Qb, *gbuf;
    cudaGetSymbolAddress((void**)&Fp,   g_Fp);
    cudaGetSymbolAddress((void**)&KV,   g_KV);
    cudaGetSymbolAddress((void**)&Wkv,  g_Wkv);
    cudaGetSymbolAddress((void**)&W2b,  g_W2b);
    cudaGetSymbolAddress((void**)&Wfb,  g_Wfb);
    cudaGetSymbolAddress((void**)&g1wb, g_g1wb);
    cudaGetSymbolAddress((void**)&g2wb, g_g2wb);
    cudaGetSymbolAddress((void**)&wb,   g_wb);
    cudaGetSymbolAddress((void**)&fCb,  g_fCb);
    cudaGetSymbolAddress((void**)&gin,  g_ginb);
    cudaGetSymbolAddress((void**)&hmid, g_hmid);
    cudaGetSymbolAddress((void**)&fCp,  g_fCp);
    cudaGetSymbolAddress((void**)&Qb,   g_Q);
    cudaGetSymbolAddress((void**)&gbuf, g_g);

    const int T = 256;
    auto nb = [](int n, int t) { return (n + t - 1) / t; };

    // weight/input converts to bf16
    cvt_k<<<nb(DD * DX / 4, T), T>>>(W1, Wkv, DD * DX / 4);
    cvt_k<<<nb(DD * DX / 4, T), T>>>(Wv, Wkv + (size_t)DD * DX, DD * DX / 4);
    cvt_k<<<nb(DD * DD / 4, T), T>>>(W2, W2b, DD * DD / 4);
    cvt_k<<<nb(DD * DF / 4, T), T>>>(Wf, Wfb, DD * DF / 4);
    cvt_k<<<nb(PHH * DX / 4, T), T>>>(g1w, g1wb, PHH * DX / 4);
    cvt_k<<<nb(DD * PHH / 4, T), T>>>(g2w, g2wb, DD * PHH / 4);
    cvt_k<<<nb(CC * DD / 4, T), T>>>(w, wb, CC * DD / 4);
    cvt_k<<<nb(CC * DF / 4, T), T>>>(fC, fCb, CC * DF / 4);
    prep_fp_k<<<nb(MKV * DX / 4, T), T>>>(F, Et, Fp);
    prep_gin_k<<<nb(CC * DX, T), T>>>(w, Et, gin);

    // small GEMMs (dependencies: fCp -> Q, KV ; gin -> hmid -> g)
    gemm_k<M_PLAIN><<<dim3(DD / 128, CC / 128), T>>>(fCb, Wfb, fCp, CC, DD, DF, nullptr, nullptr);
    gemm_k<M_ADDB><<<dim3(DD / 128, CC / 128), T>>>(wb, W2b, Qb, CC, DD, DD, fCp, beta);
    gemm_k<M_RELU><<<dim3(PHH / 128, CC / 128), T>>>(gin, g1wb, hmid, CC, PHH, DX, g1b, nullptr);
    gemm_k<M_SIG><<<dim3(DD / 128, CC / 128), T>>>(hmid, g2wb, gbuf, CC, DD, PHH, g2b, nullptr);

    // the big fused K|V projection GEMM
    gemm_k<M_KV><<<dim3(NKV / 128, MKV / 128), T>>>(Fp, Wkv, KV, MKV, NKV, DX, fCp, alpha);

    // attention + gate + normalize
    attn_k<<<CC, T>>>(KV, Qb, gbuf, w, out);
}

// round 4
// speedup vs baseline: 3.8449x; 3.8449x over previous
#include <cuda_runtime.h>
#include <cuda_bf16.h>
#include <cstdint>

// ---------------- problem dims ----------------
#define CC   2048
#define KTT  64
#define DD   1024
#define DE   128
#define DF   256
#define NH   8
#define DHH  128
#define DX   1152   // D + De
#define PHH  1024

// ---------------- scratch (__device__ globals; no allocations) ----------------
__device__ __align__(128) __nv_bfloat16 g_W2b[DD * DD];
__device__ __align__(128) __nv_bfloat16 g_Wfb[DD * DF];
__device__ __align__(128) __nv_bfloat16 g_g1wb[PHH * DX];
__device__ __align__(128) __nv_bfloat16 g_g2wb[DD * PHH];
__device__ __align__(128) __nv_bfloat16 g_wb[CC * DD];
__device__ __align__(128) __nv_bfloat16 g_fCb[CC * DF];
__device__ __align__(128) __nv_bfloat16 g_ginb[CC * DX];
__device__ __align__(128) __nv_bfloat16 g_hmid[CC * PHH];
__device__ __align__(128) __nv_bfloat16 g_Qb[CC * DD];
__device__ __align__(128) __nv_bfloat16 g_W1t[NH * DX * DHH];   // [h][x][d]
__device__ __align__(128) __nv_bfloat16 g_Wvb[DD * DX];
__device__ __align__(128) __nv_bfloat16 g_qt[(size_t)CC * NH * DX];  // 37.7 MB
__device__ __align__(128) __nv_bfloat16 g_Z[(size_t)CC * NH * DX];   // 37.7 MB
__device__ __align__(128) float g_fCp[CC * DD];
__device__ __align__(128) float g_A[CC * DD];
__device__ __align__(128) float g_g[CC * DD];

// ---------------- PTX helpers ----------------
__device__ __forceinline__ void cpasync16(void* dst, const void* src) {
    uint32_t d = (uint32_t)__cvta_generic_to_shared(dst);
    asm volatile("cp.async.cg.shared.global [%0], [%1], 16;\n" :: "r"(d), "l"(src));
}
__device__ __forceinline__ void cp_commit() {
    asm volatile("cp.async.commit_group;\n" ::: "memory");
}
template <int N>
__device__ __forceinline__ void cp_wait() {
    asm volatile("cp.async.wait_group %0;\n" :: "n"(N) : "memory");
}
__device__ __forceinline__ void ldm_x4(uint32_t* r, const void* p) {
    uint32_t a = (uint32_t)__cvta_generic_to_shared(p);
    asm volatile("ldmatrix.sync.aligned.m8n8.x4.shared.b16 {%0,%1,%2,%3}, [%4];\n"
                 : "=r"(r[0]), "=r"(r[1]), "=r"(r[2]), "=r"(r[3]) : "r"(a));
}
__device__ __forceinline__ void mma16816(float* c, const uint32_t* a, uint32_t b0, uint32_t b1) {
    asm volatile(
        "mma.sync.aligned.m16n8k16.row.col.f32.bf16.bf16.f32 "
        "{%0,%1,%2,%3},{%4,%5,%6,%7},{%8,%9},{%0,%1,%2,%3};\n"
        : "+f"(c[0]), "+f"(c[1]), "+f"(c[2]), "+f"(c[3])
        : "r"(a[0]), "r"(a[1]), "r"(a[2]), "r"(a[3]), "r"(b0), "r"(b1));
}
// bf16x2 unpack: lo exact; hi uses raw bits (mantissa noise < 2^-8, same order as bf16 rounding)
__device__ __forceinline__ float lo16(uint32_t u) { return __uint_as_float(u << 16); }
__device__ __forceinline__ float hi16(uint32_t u) { return __uint_as_float(u & 0xffff0000u); }
__device__ __forceinline__ float hi16g(uint32_t u) { return __uint_as_float(u); }
__device__ __forceinline__ uint32_t packbf2(float a, float b) {
    __nv_bfloat162 t = __floats2bfloat162_rn(a, b);
    return *(uint32_t*)&t;
}

// ---------------- prep kernels ----------------
__global__ void cvt_k(const float* __restrict__ s, __nv_bfloat16* __restrict__ d, int n4) {
    int i = blockIdx.x * blockDim.x + threadIdx.x;
    if (i >= n4) return;
    float4 f = ((const float4*)s)[i];
    __nv_bfloat162* o = (__nv_bfloat162*)(d + (size_t)i * 4);
    o[0] = __floats2bfloat162_rn(f.x, f.y);
    o[1] = __floats2bfloat162_rn(f.z, f.w);
}

// W1t[h][x][d] = bf16(W1[h*128+d][x])
__global__ void w1t_k(const float* __restrict__ W1, __nv_bfloat16* __restrict__ W1t) {
    int i = blockIdx.x * blockDim.x + threadIdx.x;
    if (i >= NH * DX * DHH) return;
    int d = i & 127;
    int x = (i >> 7) % DX;
    int h = i / (DX * DHH);
    W1t[i] = __float2bfloat16(W1[(size_t)(h * DHH + d) * DX + x]);
}

// gin = bf16(concat(w, mean_kt(Et)))
__global__ void prep_gin_k(const float* __restrict__ w, const float* __restrict__ Et,
                           __nv_bfloat16* __restrict__ gin) {
    int i = blockIdx.x * blockDim.x + threadIdx.x;
    if (i >= CC * DX) return;
    int c = i / DX, x = i - c * DX;
    float v;
    if (x < DD) {
        v = w[(size_t)c * DD + x];
    } else {
        int j = x - DD;
        const float* p = Et + (size_t)c * KTT * DE + j;
        float s = 0.f;
        #pragma unroll 8
        for (int kt = 0; kt < KTT; kt++) s += p[(size_t)kt * DE];
        v = s * (1.0f / 64.0f);
    }
    gin[i] = __float2bfloat16(v);
}

// ---------------- GEMM: C[M,N] = A[M,K] @ B[N,K]^T (bf16 in, fp32 accum, strided, batched z) ----
enum { M_PLAIN = 0, M_ADDBF = 1, M_RELU = 2, M_SIG = 3, M_BF16 = 4 };

template <int MODE>
__global__ void __launch_bounds__(256)
gemm_k(const __nv_bfloat16* __restrict__ A, const __nv_bfloat16* __restrict__ B,
       void* __restrict__ OutP, int M, int N, int K,
       int lda, int ldb, int ldc, int azs, int bzs, int czs,
       const float* __restrict__ extra, const float* __restrict__ scal) {
    __shared__ __align__(16) __nv_bfloat16 sA[2][128][40];
    __shared__ __align__(16) __nv_bfloat16 sB[2][128][40];

    const int tid  = threadIdx.x;
    const int lane = tid & 31, warp = tid >> 5;
    const int wm = (warp >> 1) << 5;
    const int wn = (warp & 1) << 6;
    const int m0 = blockIdx.y << 7, n0 = blockIdx.x << 7;
    A += (size_t)blockIdx.z * azs;
    B += (size_t)blockIdx.z * bzs;
    const int cz = blockIdx.z * czs;

    float acc[2][8][4];
    #pragma unroll
    for (int i = 0; i < 2; i++)
        #pragma unroll
        for (int j = 0; j < 8; j++)
            #pragma unroll
            for (int r = 0; r < 4; r++) acc[i][j][r] = 0.f;

    auto tile_load = [&](int buf, int kt) {
        #pragma unroll
        for (int r = 0; r < 2; r++) {
            int id  = tid + (r << 8);
            int row = id >> 2;
            int cc  = (id & 3) << 3;
            cpasync16(&sA[buf][row][cc], A + (size_t)(m0 + row) * lda + kt + cc);
            cpasync16(&sB[buf][row][cc], B + (size_t)(n0 + row) * ldb + kt + cc);
        }
    };

    tile_load(0, 0);
    cp_commit();
    const int nk = K >> 5;
    for (int t = 0; t < nk; t++) {
        if (t + 1 < nk) {
            tile_load((t + 1) & 1, (t + 1) << 5);
            cp_commit();
            cp_wait<1>();
        } else {
            cp_wait<0>();
        }
        __syncthreads();
        const int buf = t & 1;
        #pragma unroll
        for (int s = 0; s < 2; s++) {
            uint32_t af[2][4], bfr[4][4];
            #pragma unroll
            for (int i = 0; i < 2; i++)
                ldm_x4(af[i], &sA[buf][wm + (i << 4) + (lane & 15)][(s << 4) + ((lane >> 4) << 3)]);
            #pragma unroll
            for (int j = 0; j < 4; j++)
                ldm_x4(bfr[j], &sB[buf][wn + (j << 4) + (lane & 15)][(s << 4) + ((lane >> 4) << 3)]);
            #pragma unroll
            for (int i = 0; i < 2; i++)
                #pragma unroll
                for (int j = 0; j < 4; j++) {
                    mma16816(acc[i][2 * j],     af[i], bfr[j][0], bfr[j][2]);
                    mma16816(acc[i][2 * j + 1], af[i], bfr[j][1], bfr[j][3]);
                }
        }
        __syncthreads();
    }

    float sc = 0.f;
    if (MODE == M_ADDBF) sc = scal[0];
    #pragma unroll
    for (int i = 0; i < 2; i++) {
        #pragma unroll
        for (int j = 0; j < 8; j++) {
            const int colg = n0 + wn + (j << 3) + ((lane & 3) << 1);
            #pragma unroll
            for (int r2 = 0; r2 < 2; r2++) {
                const int row = m0 + wm + (i << 4) + (lane >> 2) + (r2 << 3);
                float v0 = acc[i][j][r2 * 2], v1 = acc[i][j][r2 * 2 + 1];
                const size_t oidx = (size_t)row * ldc + cz + colg;
                if (MODE == M_PLAIN) {
                    *(float2*)((float*)OutP + oidx) = make_float2(v0, v1);
                } else if (MODE == M_ADDBF) {
                    const float* fp = extra + (size_t)row * ldc + colg;
                    *(__nv_bfloat162*)((__nv_bfloat16*)OutP + oidx) =
                        __floats2bfloat162_rn(v0 + sc * fp[0], v1 + sc * fp[1]);
                } else if (MODE == M_RELU) {
                    v0 = fmaxf(v0 + extra[colg], 0.f);
                    v1 = fmaxf(v1 + extra[colg + 1], 0.f);
                    *(__nv_bfloat162*)((__nv_bfloat16*)OutP + oidx) =
                        __floats2bfloat162_rn(v0, v1);
                } else if (MODE == M_SIG) {
                    v0 = 1.f / (1.f + __expf(-(v0 + extra[colg])));
                    v1 = 1.f / (1.f + __expf(-(v1 + extra[colg + 1])));
                    *(float2*)((float*)OutP + oidx) = make_float2(v0, v1);
                } else { // M_BF16
                    *(__nv_bfloat162*)((__nv_bfloat16*)OutP + oidx) =
                        __floats2bfloat162_rn(v0, v1);
                }
            }
        }
    }
}

// ---------------- fused per-c attention core ----------------
// smem: Fp[64][1160] bf16 (padded row=580 u32), qt[8][1160] bf16, scores[8][64] f32
#define FPW 580                        // padded u32 words per row
#define SM_FP 0
#define SM_QT (64 * FPW)               // 37120
#define SM_SC (SM_QT + 8 * FPW)        // 41760 (u32 index)
#define ATTN_SMEM ((SM_SC + 512) * 4)  // 169088 bytes

__global__ void __launch_bounds__(256, 1)
attn_fused_k(const float* __restrict__ F, const float* __restrict__ Et,
             const __nv_bfloat16* __restrict__ qtg, __nv_bfloat16* __restrict__ Z) {
    extern __shared__ uint32_t smem_u[];
    uint32_t* fp_s = smem_u + SM_FP;
    uint32_t* qt_s = smem_u + SM_QT;
    float*    sc_s = (float*)(smem_u + SM_SC);

    const int c = blockIdx.x;
    const int tid = threadIdx.x;
    const int wid = tid >> 5, lane = tid & 31;

    // ---- load F|Et -> bf16 smem (64 rows x 1152) ----
    for (int i = tid; i < 64 * 288; i += 256) {
        int row = i / 288, j = i - row * 288;
        float4 v = (j < 256)
            ? ((const float4*)F)[((size_t)c * 64 + row) * 256 + j]
            : ((const float4*)Et)[((size_t)c * 64 + row) * 32 + (j - 256)];
        uint2 pk;
        pk.x = packbf2(v.x, v.y);
        pk.y = packbf2(v.z, v.w);
        *(uint2*)(fp_s + row * FPW + j * 2) = pk;
    }
    // ---- load qt[c] (8 x 1152 bf16) ----
    for (int i = tid; i < 8 * 288; i += 256) {
        int row = i / 288, j = i - row * 288;
        uint2 v = ((const uint2*)(qtg + (size_t)c * (NH * DX) + row * DX))[j];
        *(uint2*)(qt_s + row * FPW + j * 2) = v;
    }
    __syncthreads();

    // ---- phase 1: scores[h][k] = qt[h]·Fp[k] * rsqrt(dh) ----
    {
        const int h  = tid & 7;
        const int k0 = tid >> 3;          // 0..31 ; also handles k0+32
        const uint2* qp = (const uint2*)(qt_s + h * FPW);
        const uint2* f0 = (const uint2*)(fp_s + k0 * FPW);
        const uint2* f1 = (const uint2*)(fp_s + (k0 + 32) * FPW);
        float a00 = 0.f, a01 = 0.f, a10 = 0.f, a11 = 0.f;
        #pragma unroll 4
        for (int j = 0; j < 288; j++) {
            uint2 q = qp[j], u = f0[j], v = f1[j];
            float qx0 = lo16(q.x), qx1 = hi16(q.x);
            float qy0 = lo16(q.y), qy1 = hi16(q.y);
            a00 += qx0 * lo16(u.x);  a00 += qx1 * hi16g(u.x);
            a01 += qy0 * lo16(u.y);  a01 += qy1 * hi16g(u.y);
            a10 += qx0 * lo16(v.x);  a10 += qx1 * hi16g(v.x);
            a11 += qy0 * lo16(v.y);  a11 += qy1 * hi16g(v.y);
        }
        sc_s[h * 64 + k0]      = (a00 + a01) * 0.08838834764831845f;
        sc_s[h * 64 + k0 + 32] = (a10 + a11) * 0.08838834764831845f;
    }
    __syncthreads();

    // ---- phase 2: softmax per head (warp = head) ----
    {
        const int h = wid;
        float v0 = sc_s[h * 64 + lane], v1 = sc_s[h * 64 + lane + 32];
        float m = fmaxf(v0, v1);
        #pragma unroll
        for (int o = 16; o; o >>= 1) m = fmaxf(m, __shfl_xor_sync(0xffffffffu, m, o));
        float e0 = __expf(v0 - m), e1 = __expf(v1 - m);
        float s = e0 + e1;
        #pragma unroll
        for (int o = 16; o; o >>= 1) s += __shfl_xor_sync(0xffffffffu, s, o);
        float inv = 1.f / s;
        sc_s[h * 64 + lane]      = e0 * inv;
        sc_s[h * 64 + lane + 32] = e1 * inv;
    }
    __syncthreads();

    // ---- phase 3: z[h][x] = sum_k attn[h][k] * Fp[k][x]  (warp = head) ----
    {
        const int h = wid;
        float za[18], zb[18];
        #pragma unroll
        for (int j = 0; j < 18; j++) { za[j] = 0.f; zb[j] = 0.f; }
        for (int k = 0; k < 64; k++) {
            const float p = sc_s[h * 64 + k];
            const uint32_t* fr = fp_s + k * FPW;
            #pragma unroll
            for (int j = 0; j < 18; j++) {
                uint32_t u = fr[j * 32 + lane];
                za[j] += p * lo16(u);
                zb[j] += p * hi16g(u);
            }
        }
        uint32_t* zo = (uint32_t*)(Z + (size_t)c * (NH * DX) + h * DX);
        #pragma unroll
        for (int j = 0; j < 18; j++)
            zo[j * 32 + lane] = packbf2(za[j], zb[j]);
    }
}

// ---------------- finalize: out = normalize(w + g*A) ----------------
__global__ void __launch_bounds__(256)
finalize_k(const float* __restrict__ w, const float* __restrict__ g,
           const float* __restrict__ A, float* __restrict__ out) {
    const int c = blockIdx.x, tid = threadIdx.x;
    const int wid = tid >> 5, lane = tid & 31;
    __shared__ float sred[8];
    float u[4]; float ss = 0.f;
    #pragma unroll
    for (int i = 0; i < 4; i++) {
        size_t idx = (size_t)c * DD + i * 256 + tid;
        u[i] = w[idx] + g[idx] * A[idx];
        ss += u[i] * u[i];
    }
    #pragma unroll
    for (int o = 16; o; o >>= 1) ss += __shfl_xor_sync(0xffffffffu, ss, o);
    if (lane == 0) sred[wid] = ss;
    __syncthreads();
    float tot = 0.f;
    #pragma unroll
    for (int h = 0; h < 8; h++) tot += sred[h];
    float inv = 1.f / fmaxf(sqrtf(tot), 1e-12f);
    #pragma unroll
    for (int i = 0; i < 4; i++)
        out[(size_t)c * DD + i * 256 + tid] = u[i] * inv;
}

// ---------------- launch ----------------
extern "C" void kernel_launch(void* const* d_in, const int* in_sizes, int n_in,
                              void* d_out, int out_size) {
    const float* w   = (const float*)d_in[0];
    const float* F   = (const float*)d_in[1];
    const float* Et  = (const float*)d_in[2];
    const float* fC  = (const float*)d_in[3];
    const float* W1  = (const float*)d_in[4];
    const float* W2  = (const float*)d_in[5];
    const float* Wv  = (const float*)d_in[6];
    const float* Wf  = (const float*)d_in[7];
    // alpha (d_in[8]) cancels in softmax — unused
    const float* beta = (const float*)d_in[9];
    const float* g1w = (const float*)d_in[10];
    const float* g1b = (const float*)d_in[11];
    const float* g2w = (const float*)d_in[12];
    const float* g2b = (const float*)d_in[13];
    float* out = (float*)d_out;

    __nv_bfloat16 *W2b, *Wfb, *g1wb, *g2wb, *wb, *fCb, *gin, *hmid, *Qb, *W1t, *Wvb, *qt, *Z;
    float *fCp, *A, *gbuf;
    cudaGetSymbolAddress((void**)&W2b,  g_W2b);
    cudaGetSymbolAddress((void**)&Wfb,  g_Wfb);
    cudaGetSymbolAddress((void**)&g1wb, g_g1wb);
    cudaGetSymbolAddress((void**)&g2wb, g_g2wb);
    cudaGetSymbolAddress((void**)&wb,   g_wb);
    cudaGetSymbolAddress((void**)&fCb,  g_fCb);
    cudaGetSymbolAddress((void**)&gin,  g_ginb);
    cudaGetSymbolAddress((void**)&hmid, g_hmid);
    cudaGetSymbolAddress((void**)&Qb,   g_Qb);
    cudaGetSymbolAddress((void**)&W1t,  g_W1t);
    cudaGetSymbolAddress((void**)&Wvb,  g_Wvb);
    cudaGetSymbolAddress((void**)&qt,   g_qt);
    cudaGetSymbolAddress((void**)&Z,    g_Z);
    cudaGetSymbolAddress((void**)&fCp,  g_fCp);
    cudaGetSymbolAddress((void**)&A,    g_A);
    cudaGetSymbolAddress((void**)&gbuf, g_g);

    cudaFuncSetAttribute(attn_fused_k, cudaFuncAttributeMaxDynamicSharedMemorySize, ATTN_SMEM);

    const int T = 256;
    auto nb = [](int n, int t) { return (n + t - 1) / t; };

    // converts / transposes / gate input
    cvt_k<<<nb(DD * DD / 4, T), T>>>(W2, W2b, DD * DD / 4);
    cvt_k<<<nb(DD * DF / 4, T), T>>>(Wf, Wfb, DD * DF / 4);
    cvt_k<<<nb(PHH * DX / 4, T), T>>>(g1w, g1wb, PHH * DX / 4);
    cvt_k<<<nb(DD * PHH / 4, T), T>>>(g2w, g2wb, DD * PHH / 4);
    cvt_k<<<nb(CC * DD / 4, T), T>>>(w, wb, CC * DD / 4);
    cvt_k<<<nb(CC * DF / 4, T), T>>>(fC, fCb, CC * DF / 4);
    cvt_k<<<nb(DD * DX / 4, T), T>>>(Wv, Wvb, DD * DX / 4);
    w1t_k<<<nb(NH * DX * DHH, T), T>>>(W1, W1t);
    prep_gin_k<<<nb(CC * DX, T), T>>>(w, Et, gin);

    // fCp = fC @ Wf^T                               [2048,1024] f32
    gemm_k<M_PLAIN><<<dim3(8, 16, 1), T>>>(fCb, Wfb, fCp, CC, DD, DF,
                                           DF, DF, DD, 0, 0, 0, nullptr, nullptr);
    // Q = w @ W2^T + beta*fCp  -> bf16              [2048,1024]
    gemm_k<M_ADDBF><<<dim3(8, 16, 1), T>>>(wb, W2b, Qb, CC, DD, DD,
                                           DD, DD, DD, 0, 0, 0, fCp, beta);
    // qt[:,h,:] = Qh[:,h,:] @ W1_h  -> bf16         [2048, 8, 1152]
    gemm_k<M_BF16><<<dim3(9, 16, 8), T>>>(Qb, W1t, qt, CC, DX, DHH,
                                          DD, DHH, NH * DX, DHH, DX * DHH, DX,
                                          nullptr, nullptr);
    // gate MLP
    gemm_k<M_RELU><<<dim3(8, 16, 1), T>>>(gin, g1wb, hmid, CC, PHH, DX,
                                          DX, DX, PHH, 0, 0, 0, g1b, nullptr);
    gemm_k<M_SIG><<<dim3(8, 16, 1), T>>>(hmid, g2wb, gbuf, CC, DD, PHH,
                                         PHH, PHH, DD, 0, 0, 0, g2b, nullptr);

    // fused attention core: scores -> softmax -> z  (reads F/Et directly)
    attn_fused_k<<<CC, T, ATTN_SMEM>>>(F, Et, qt, Z);

    // A[:,h,:] = Z[:,h,:] @ Wv_h^T  -> f32          [2048,1024]
    gemm_k<M_PLAIN><<<dim3(1, 16, 8), T>>>(Z, Wvb, A, CC, DHH, DX,
                                           NH * DX, DX, DD, DX, DHH * DX, DHH,
                                           nullptr, nullptr);

    // out = normalize(w + g*A)
    finalize_k<<<CC, T>>>(w, gbuf, A, out);
}

// round 5
// speedup vs baseline: 5.1524x; 1.3401x over previous
#include <cuda_runtime.h>
#include <cuda_bf16.h>
#include <cstdint>

// ---------------- problem dims ----------------
#define CC   2048
#define KTT  64
#define DD   1024
#define DE   128
#define DF   256
#define NH   8
#define DHH  128
#define DX   1152   // D + De
#define PHH  1024
#define KQC  1280   // D + Df (merged Q gemm K)

// ---------------- scratch (__device__ globals; no allocations) ----------------
__device__ __align__(128) __nv_bfloat16 g_W2f[DD * KQC];            // [W2 | beta*Wf]
__device__ __align__(128) __nv_bfloat16 g_wfc[CC * KQC];            // [w | fC]
__device__ __align__(128) __nv_bfloat16 g_g1wb[PHH * DX];
__device__ __align__(128) __nv_bfloat16 g_g2wb[DD * PHH];
__device__ __align__(128) __nv_bfloat16 g_ginb[CC * DX];
__device__ __align__(128) __nv_bfloat16 g_hmid[CC * PHH];
__device__ __align__(128) __nv_bfloat16 g_Qb[CC * DD];
__device__ __align__(128) __nv_bfloat16 g_W1t[NH * DX * DHH];       // [h][x][d]
__device__ __align__(128) __nv_bfloat16 g_Wvb[DD * DX];
__device__ __align__(128) __nv_bfloat16 g_qt[(size_t)CC * NH * DX];
__device__ __align__(128) __nv_bfloat16 g_Z[(size_t)CC * NH * DX];
__device__ __align__(128) float g_A[CC * DD];
__device__ __align__(128) float g_g[CC * DD];

// ---------------- PTX helpers ----------------
__device__ __forceinline__ void cpasync16(void* dst, const void* src) {
    uint32_t d = (uint32_t)__cvta_generic_to_shared(dst);
    asm volatile("cp.async.cg.shared.global [%0], [%1], 16;\n" :: "r"(d), "l"(src));
}
__device__ __forceinline__ void cp_commit() {
    asm volatile("cp.async.commit_group;\n" ::: "memory");
}
template <int N>
__device__ __forceinline__ void cp_wait() {
    asm volatile("cp.async.wait_group %0;\n" :: "n"(N) : "memory");
}
__device__ __forceinline__ void ldm_x4(uint32_t* r, const void* p) {
    uint32_t a = (uint32_t)__cvta_generic_to_shared(p);
    asm volatile("ldmatrix.sync.aligned.m8n8.x4.shared.b16 {%0,%1,%2,%3}, [%4];\n"
                 : "=r"(r[0]), "=r"(r[1]), "=r"(r[2]), "=r"(r[3]) : "r"(a));
}
__device__ __forceinline__ void ldm_x4t(uint32_t* r, const void* p) {
    uint32_t a = (uint32_t)__cvta_generic_to_shared(p);
    asm volatile("ldmatrix.sync.aligned.m8n8.x4.trans.shared.b16 {%0,%1,%2,%3}, [%4];\n"
                 : "=r"(r[0]), "=r"(r[1]), "=r"(r[2]), "=r"(r[3]) : "r"(a));
}
__device__ __forceinline__ void mma16816(float* c, const uint32_t* a, uint32_t b0, uint32_t b1) {
    asm volatile(
        "mma.sync.aligned.m16n8k16.row.col.f32.bf16.bf16.f32 "
        "{%0,%1,%2,%3},{%4,%5,%6,%7},{%8,%9},{%0,%1,%2,%3};\n"
        : "+f"(c[0]), "+f"(c[1]), "+f"(c[2]), "+f"(c[3])
        : "r"(a[0]), "r"(a[1]), "r"(a[2]), "r"(a[3]), "r"(b0), "r"(b1));
}
__device__ __forceinline__ uint32_t packbf2(float a, float b) {
    __nv_bfloat162 t = __floats2bfloat162_rn(a, b);
    return *(uint32_t*)&t;
}

// ---------------- prep kernels ----------------
__global__ void cvt_k(const float* __restrict__ s, __nv_bfloat16* __restrict__ d, int n4) {
    int i = blockIdx.x * blockDim.x + threadIdx.x;
    if (i >= n4) return;
    float4 f = ((const float4*)s)[i];
    __nv_bfloat162* o = (__nv_bfloat162*)(d + (size_t)i * 4);
    o[0] = __floats2bfloat162_rn(f.x, f.y);
    o[1] = __floats2bfloat162_rn(f.z, f.w);
}

// W2f[d][0:1024] = W2[d]; W2f[d][1024:1280] = beta * Wf[d]
__global__ void w2f_k(const float* __restrict__ W2, const float* __restrict__ Wf,
                      const float* __restrict__ beta, __nv_bfloat16* __restrict__ O) {
    int i = blockIdx.x * blockDim.x + threadIdx.x;
    if (i >= DD * (KQC / 4)) return;
    int row = i / 320, j = i - row * 320;
    float sc = 1.f;
    float4 f;
    if (j < 256) f = ((const float4*)W2)[(size_t)row * 256 + j];
    else { f = ((const float4*)Wf)[(size_t)row * 64 + (j - 256)]; sc = beta[0]; }
    __nv_bfloat162* o = (__nv_bfloat162*)(O + (size_t)row * KQC + j * 4);
    o[0] = __floats2bfloat162_rn(f.x * sc, f.y * sc);
    o[1] = __floats2bfloat162_rn(f.z * sc, f.w * sc);
}

// wfc[c][0:1024] = w[c]; wfc[c][1024:1280] = fC[c]
__global__ void wfc_k(const float* __restrict__ w, const float* __restrict__ fC,
                      __nv_bfloat16* __restrict__ O) {
    int i = blockIdx.x * blockDim.x + threadIdx.x;
    if (i >= CC * (KQC / 4)) return;
    int row = i / 320, j = i - row * 320;
    float4 f = (j < 256) ? ((const float4*)w)[(size_t)row * 256 + j]
                         : ((const float4*)fC)[(size_t)row * 64 + (j - 256)];
    __nv_bfloat162* o = (__nv_bfloat162*)(O + (size_t)row * KQC + j * 4);
    o[0] = __floats2bfloat162_rn(f.x, f.y);
    o[1] = __floats2bfloat162_rn(f.z, f.w);
}

// W1t[h][x][d] = bf16(W1[h*128+d][x])
__global__ void w1t_k(const float* __restrict__ W1, __nv_bfloat16* __restrict__ W1t) {
    int i = blockIdx.x * blockDim.x + threadIdx.x;
    if (i >= NH * DX * DHH) return;
    int d = i & 127;
    int x = (i >> 7) % DX;
    int h = i / (DX * DHH);
    W1t[i] = __float2bfloat16(W1[(size_t)(h * DHH + d) * DX + x]);
}

// gin = bf16(concat(w, mean_kt(Et)))
__global__ void prep_gin_k(const float* __restrict__ w, const float* __restrict__ Et,
                           __nv_bfloat16* __restrict__ gin) {
    int i = blockIdx.x * blockDim.x + threadIdx.x;
    if (i >= CC * DX) return;
    int c = i / DX, x = i - c * DX;
    float v;
    if (x < DD) {
        v = w[(size_t)c * DD + x];
    } else {
        int j = x - DD;
        const float* p = Et + (size_t)c * KTT * DE + j;
        float s = 0.f;
        #pragma unroll 8
        for (int kt = 0; kt < KTT; kt++) s += p[(size_t)kt * DE];
        v = s * (1.0f / 64.0f);
    }
    gin[i] = __float2bfloat16(v);
}

// ---------------- GEMM: C[M,N] = A[M,K] @ B[N,K]^T (bf16 in, fp32 accum, strided batch) ----
enum { M_PLAIN = 0, M_RELU = 2, M_SIG = 3, M_BF16 = 4 };

template <int MODE>
__global__ void __launch_bounds__(256)
gemm_k(const __nv_bfloat16* __restrict__ A, const __nv_bfloat16* __restrict__ B,
       void* __restrict__ OutP, int M, int N, int K,
       int lda, int ldb, int ldc, int azs, int bzs, int czs,
       const float* __restrict__ extra) {
    __shared__ __align__(16) __nv_bfloat16 sA[2][128][40];
    __shared__ __align__(16) __nv_bfloat16 sB[2][128][40];

    const int tid  = threadIdx.x;
    const int lane = tid & 31, warp = tid >> 5;
    const int wm = (warp >> 1) << 5;
    const int wn = (warp & 1) << 6;
    const int m0 = blockIdx.y << 7, n0 = blockIdx.x << 7;
    A += (size_t)blockIdx.z * azs;
    B += (size_t)blockIdx.z * bzs;
    const int cz = blockIdx.z * czs;

    float acc[2][8][4];
    #pragma unroll
    for (int i = 0; i < 2; i++)
        #pragma unroll
        for (int j = 0; j < 8; j++)
            #pragma unroll
            for (int r = 0; r < 4; r++) acc[i][j][r] = 0.f;

    auto tile_load = [&](int buf, int kt) {
        #pragma unroll
        for (int r = 0; r < 2; r++) {
            int id  = tid + (r << 8);
            int row = id >> 2;
            int cc  = (id & 3) << 3;
            cpasync16(&sA[buf][row][cc], A + (size_t)(m0 + row) * lda + kt + cc);
            cpasync16(&sB[buf][row][cc], B + (size_t)(n0 + row) * ldb + kt + cc);
        }
    };

    tile_load(0, 0);
    cp_commit();
    const int nk = K >> 5;
    for (int t = 0; t < nk; t++) {
        if (t + 1 < nk) {
            tile_load((t + 1) & 1, (t + 1) << 5);
            cp_commit();
            cp_wait<1>();
        } else {
            cp_wait<0>();
        }
        __syncthreads();
        const int buf = t & 1;
        #pragma unroll
        for (int s = 0; s < 2; s++) {
            uint32_t af[2][4], bfr[4][4];
            #pragma unroll
            for (int i = 0; i < 2; i++)
                ldm_x4(af[i], &sA[buf][wm + (i << 4) + (lane & 15)][(s << 4) + ((lane >> 4) << 3)]);
            #pragma unroll
            for (int j = 0; j < 4; j++)
                ldm_x4(bfr[j], &sB[buf][wn + (j << 4) + (lane & 15)][(s << 4) + ((lane >> 4) << 3)]);
            #pragma unroll
            for (int i = 0; i < 2; i++)
                #pragma unroll
                for (int j = 0; j < 4; j++) {
                    mma16816(acc[i][2 * j],     af[i], bfr[j][0], bfr[j][2]);
                    mma16816(acc[i][2 * j + 1], af[i], bfr[j][1], bfr[j][3]);
                }
        }
        __syncthreads();
    }

    #pragma unroll
    for (int i = 0; i < 2; i++) {
        #pragma unroll
        for (int j = 0; j < 8; j++) {
            const int colg = n0 + wn + (j << 3) + ((lane & 3) << 1);
            #pragma unroll
            for (int r2 = 0; r2 < 2; r2++) {
                const int row = m0 + wm + (i << 4) + (lane >> 2) + (r2 << 3);
                float v0 = acc[i][j][r2 * 2], v1 = acc[i][j][r2 * 2 + 1];
                const size_t oidx = (size_t)row * ldc + cz + colg;
                if (MODE == M_PLAIN) {
                    *(float2*)((float*)OutP + oidx) = make_float2(v0, v1);
                } else if (MODE == M_RELU) {
                    v0 = fmaxf(v0 + extra[colg], 0.f);
                    v1 = fmaxf(v1 + extra[colg + 1], 0.f);
                    *(__nv_bfloat162*)((__nv_bfloat16*)OutP + oidx) =
                        __floats2bfloat162_rn(v0, v1);
                } else if (MODE == M_SIG) {
                    v0 = 1.f / (1.f + __expf(-(v0 + extra[colg])));
                    v1 = 1.f / (1.f + __expf(-(v1 + extra[colg + 1])));
                    *(float2*)((float*)OutP + oidx) = make_float2(v0, v1);
                } else { // M_BF16
                    *(__nv_bfloat162*)((__nv_bfloat16*)OutP + oidx) =
                        __floats2bfloat162_rn(v0, v1);
                }
            }
        }
    }
}

// ---------------- fused per-c attention core (mma.sync) ----------------
// smem (u32 idx): Fp[64][1160 bf16] rows of 2320B; qt[8][1160 bf16]; scores f32 [8][64];
// attn bf16 [16][72] (rows 8-15 zero, 144B row stride: 16B-aligned, bank-staggered)
#define FPW 580
#define SM_FP 0
#define SM_QT (64 * FPW)              // 37120
#define SM_SC (SM_QT + 8 * FPW)       // 41760
#define SM_AT (SM_SC + 512)           // 42272
#define ATTN_SMEM ((SM_AT + 576) * 4) // 171392 bytes

__global__ void __launch_bounds__(256, 1)
attn_fused_k(const float* __restrict__ F, const float* __restrict__ Et,
             const __nv_bfloat16* __restrict__ qtg, __nv_bfloat16* __restrict__ Z) {
    extern __shared__ uint32_t smem_u[];
    uint32_t* fp_s = smem_u + SM_FP;
    uint32_t* qt_s = smem_u + SM_QT;
    float*    sc_s = (float*)(smem_u + SM_SC);
    __nv_bfloat16* at_s = (__nv_bfloat16*)(smem_u + SM_AT);

    const int c = blockIdx.x;
    const int tid = threadIdx.x;
    const int wid = tid >> 5, lane = tid & 31;

    // ---- load F|Et -> bf16 smem (64 rows x 1152) ----
    for (int i = tid; i < 64 * 288; i += 256) {
        int row = i / 288, j = i - row * 288;
        float4 v = (j < 256)
            ? ((const float4*)F)[((size_t)c * 64 + row) * 256 + j]
            : ((const float4*)Et)[((size_t)c * 64 + row) * 32 + (j - 256)];
        uint2 pk;
        pk.x = packbf2(v.x, v.y);
        pk.y = packbf2(v.z, v.w);
        *(uint2*)(fp_s + row * FPW + j * 2) = pk;
    }
    // ---- load qt[c] (8 x 1152 bf16) ----
    for (int i = tid; i < 8 * 288; i += 256) {
        int row = i / 288, j = i - row * 288;
        uint2 v = ((const uint2*)(qtg + (size_t)c * (NH * DX) + row * DX))[j];
        *(uint2*)(qt_s + row * FPW + j * 2) = v;
    }
    __syncthreads();

    // ---- phase 1: scores[64,8] = Fp @ qt^T via mma (warps 0-3, one m16 tile each) ----
    if (wid < 4) {
        const char* aP = (const char*)fp_s + (wid * 16 + (lane & 15)) * 2320 + (lane >> 4) * 16;
        const char* bP = (const char*)qt_s + (lane & 7) * 2320 + (lane >> 4) * 16;
        float cacc[4] = {0.f, 0.f, 0.f, 0.f};
        #pragma unroll 8
        for (int kk = 0; kk < 72; kk++) {
            uint32_t a[4], b[4];
            ldm_x4(a, aP + kk * 32);
            ldm_x4(b, bP + kk * 32);
            mma16816(cacc, a, b[0], b[2]);
        }
        const int kr = wid * 16 + (lane >> 2);
        const int h0 = (lane & 3) << 1;
        sc_s[h0 * 64 + kr]           = cacc[0];
        sc_s[(h0 + 1) * 64 + kr]     = cacc[1];
        sc_s[h0 * 64 + kr + 8]       = cacc[2];
        sc_s[(h0 + 1) * 64 + kr + 8] = cacc[3];
    } else {
        // zero attn rows 8-15 (pad rows for m16 A fragment)
        uint32_t* zp = (uint32_t*)(at_s + 8 * 72);
        for (int i = tid - 128; i < 288; i += 128) zp[i] = 0;
    }
    __syncthreads();

    // ---- phase 2: softmax per head (warp = head), write bf16 attn ----
    {
        const float sc = 0.08838834764831845f;
        float v0 = sc_s[wid * 64 + lane] * sc, v1 = sc_s[wid * 64 + lane + 32] * sc;
        float m = fmaxf(v0, v1);
        #pragma unroll
        for (int o = 16; o; o >>= 1) m = fmaxf(m, __shfl_xor_sync(0xffffffffu, m, o));
        float e0 = __expf(v0 - m), e1 = __expf(v1 - m);
        float s = e0 + e1;
        #pragma unroll
        for (int o = 16; o; o >>= 1) s += __shfl_xor_sync(0xffffffffu, s, o);
        float inv = 1.f / s;
        at_s[wid * 72 + lane]      = __float2bfloat16(e0 * inv);
        at_s[wid * 72 + lane + 32] = __float2bfloat16(e1 * inv);
    }
    __syncthreads();

    // ---- phase 3: z[8,1152] = attn @ Fp via mma, B from Fp with ldmatrix.trans ----
    {
        uint32_t afr[4][4];
        const char* aP = (const char*)at_s + (lane & 15) * 144 + (lane >> 4) * 16;
        #pragma unroll
        for (int kk = 0; kk < 4; kk++) ldm_x4(afr[kk], aP + kk * 32);

        const int brow = (lane & 7) + ((lane >> 3) & 1) * 8;   // temporal row within k-step
        const int bcol = (lane >> 4) * 8;                       // x sub-column
        #pragma unroll
        for (int xt = 0; xt < 9; xt++) {
            const int x0 = (wid * 9 + xt) * 16;
            const char* bP = (const char*)fp_s + brow * 2320 + (x0 + bcol) * 2;
            float c0[4] = {0.f, 0.f, 0.f, 0.f}, c1[4] = {0.f, 0.f, 0.f, 0.f};
            #pragma unroll
            for (int kk = 0; kk < 4; kk++) {
                uint32_t b[4];
                ldm_x4t(b, bP + kk * 16 * 2320);
                mma16816(c0, afr[kk], b[0], b[1]);
                mma16816(c1, afr[kk], b[2], b[3]);
            }
            const int h = lane >> 2, xo = (lane & 3);           // cols 2*xo, 2*xo+1
            uint32_t* zo = (uint32_t*)(Z + (size_t)c * (NH * DX) + h * DX + x0);
            zo[xo]     = packbf2(c0[0], c0[1]);
            zo[xo + 4] = packbf2(c1[0], c1[1]);
        }
    }
}

// ---------------- finalize: out = normalize(w + g*A) ----------------
__global__ void __launch_bounds__(256)
finalize_k(const float* __restrict__ w, const float* __restrict__ g,
           const float* __restrict__ A, float* __restrict__ out) {
    const int c = blockIdx.x, tid = threadIdx.x;
    const int wid = tid >> 5, lane = tid & 31;
    __shared__ float sred[8];
    float u[4]; float ss = 0.f;
    #pragma unroll
    for (int i = 0; i < 4; i++) {
        size_t idx = (size_t)c * DD + i * 256 + tid;
        u[i] = w[idx] + g[idx] * A[idx];
        ss += u[i] * u[i];
    }
    #pragma unroll
    for (int o = 16; o; o >>= 1) ss += __shfl_xor_sync(0xffffffffu, ss, o);
    if (lane == 0) sred[wid] = ss;
    __syncthreads();
    float tot = 0.f;
    #pragma unroll
    for (int h = 0; h < 8; h++) tot += sred[h];
    float inv = 1.f / fmaxf(sqrtf(tot), 1e-12f);
    #pragma unroll
    for (int i = 0; i < 4; i++)
        out[(size_t)c * DD + i * 256 + tid] = u[i] * inv;
}

// ---------------- launch ----------------
extern "C" void kernel_launch(void* const* d_in, const int* in_sizes, int n_in,
                              void* d_out, int out_size) {
    const float* w   = (const float*)d_in[0];
    const float* F   = (const float*)d_in[1];
    const float* Et  = (const float*)d_in[2];
    const float* fC  = (const float*)d_in[3];
    const float* W1  = (const float*)d_in[4];
    const float* W2  = (const float*)d_in[5];
    const float* Wv  = (const float*)d_in[6];
    const float* Wf  = (const float*)d_in[7];
    // alpha (d_in[8]) cancels in softmax — unused
    const float* beta = (const float*)d_in[9];
    const float* g1w = (const float*)d_in[10];
    const float* g1b = (const float*)d_in[11];
    const float* g2w = (const float*)d_in[12];
    const float* g2b = (const float*)d_in[13];
    float* out = (float*)d_out;

    __nv_bfloat16 *W2f, *wfc, *g1wb, *g2wb, *gin, *hmid, *Qb, *W1t, *Wvb, *qt, *Z;
    float *A, *gbuf;
    cudaGetSymbolAddress((void**)&W2f,  g_W2f);
    cudaGetSymbolAddress((void**)&wfc,  g_wfc);
    cudaGetSymbolAddress((void**)&g1wb, g_g1wb);
    cudaGetSymbolAddress((void**)&g2wb, g_g2wb);
    cudaGetSymbolAddress((void**)&gin,  g_ginb);
    cudaGetSymbolAddress((void**)&hmid, g_hmid);
    cudaGetSymbolAddress((void**)&Qb,   g_Qb);
    cudaGetSymbolAddress((void**)&W1t,  g_W1t);
    cudaGetSymbolAddress((void**)&Wvb,  g_Wvb);
    cudaGetSymbolAddress((void**)&qt,   g_qt);
    cudaGetSymbolAddress((void**)&Z,    g_Z);
    cudaGetSymbolAddress((void**)&A,    g_A);
    cudaGetSymbolAddress((void**)&gbuf, g_g);

    cudaFuncSetAttribute(attn_fused_k, cudaFuncAttributeMaxDynamicSharedMemorySize, ATTN_SMEM);

    const int T = 256;
    auto nb = [](int n, int t) { return (n + t - 1) / t; };

    // prep
    w2f_k<<<nb(DD * KQC / 4, T), T>>>(W2, Wf, beta, W2f);
    wfc_k<<<nb(CC * KQC / 4, T), T>>>(w, fC, wfc);
    cvt_k<<<nb(PHH * DX / 4, T), T>>>(g1w, g1wb, PHH * DX / 4);
    cvt_k<<<nb(DD * PHH / 4, T), T>>>(g2w, g2wb, DD * PHH / 4);
    cvt_k<<<nb(DD * DX / 4, T), T>>>(Wv, Wvb, DD * DX / 4);
    w1t_k<<<nb(NH * DX * DHH, T), T>>>(W1, W1t);
    prep_gin_k<<<nb(CC * DX, T), T>>>(w, Et, gin);

    // Q = [w|fC] @ [W2|beta*Wf]^T  -> bf16   [2048,1024], K=1280
    gemm_k<M_BF16><<<dim3(8, 16, 1), T>>>(wfc, W2f, Qb, CC, DD, KQC,
                                          KQC, KQC, DD, 0, 0, 0, nullptr);
    // qt[:,h,:] = Qh[:,h,:] @ W1_h -> bf16   [2048, 8, 1152], K=128
    gemm_k<M_BF16><<<dim3(9, 16, 8), T>>>(Qb, W1t, qt, CC, DX, DHH,
                                          DD, DHH, NH * DX, DHH, DX * DHH, DX, nullptr);
    // gate MLP
    gemm_k<M_RELU><<<dim3(8, 16, 1), T>>>(gin, g1wb, hmid, CC, PHH, DX,
                                          DX, DX, PHH, 0, 0, 0, g1b);
    gemm_k<M_SIG><<<dim3(8, 16, 1), T>>>(hmid, g2wb, gbuf, CC, DD, PHH,
                                         PHH, PHH, DD, 0, 0, 0, g2b);

    // fused attention core (mma.sync): scores -> softmax -> z
    attn_fused_k<<<CC, T, ATTN_SMEM>>>(F, Et, qt, Z);

    // A[:,h,:] = Z[:,h,:] @ Wv_h^T -> f32    [2048,1024]
    gemm_k<M_PLAIN><<<dim3(1, 16, 8), T>>>(Z, Wvb, A, CC, DHH, DX,
                                           NH * DX, DX, DD, DX, DHH * DX, DHH, nullptr);

    // out = normalize(w + g*A)
    finalize_k<<<CC, T>>>(w, gbuf, A, out);
}

// round 6
// speedup vs baseline: 5.2917x; 1.0270x over previous
#include <cuda_runtime.h>
#include <cuda_bf16.h>
#include <cstdint>

// ---------------- problem dims ----------------
#define CC   2048
#define KTT  64
#define DD   1024
#define DE   128
#define DF   256
#define NH   8
#define DHH  128
#define DX   1152   // D + De
#define PHH  1024
#define KQM  1408   // D + Df + De  (merged Q/gate1 GEMM K)

// ---------------- scratch (__device__ globals; no allocations) ----------------
__device__ __align__(128) __nv_bfloat16 g_Wc[2048 * KQM];        // [W2|b*Wf|0 ; g1w_D|0|g1w_De]
__device__ __align__(128) __nv_bfloat16 g_wfm[CC * KQM];         // [w | fC | mean(Et)]
__device__ __align__(128) __nv_bfloat16 g_QH[CC * 2048];         // [Q | hmid]
__device__ __align__(128) __nv_bfloat16 g_W1t[NH * DX * DHH];    // [h][x][d]
__device__ __align__(128) __nv_bfloat16 g_Wvb[DD * DX];
__device__ __align__(128) __nv_bfloat16 g_g2wb[DD * PHH];
__device__ __align__(128) __nv_bfloat16 g_qt[(size_t)CC * NH * DX];
__device__ __align__(128) __nv_bfloat16 g_Z[(size_t)CC * NH * DX];
__device__ __align__(128) float g_g[CC * DD];
__device__ __align__(128) float g_U[CC * DD];

// ---------------- PTX helpers ----------------
__device__ __forceinline__ void cpasync16(void* dst, const void* src) {
    uint32_t d = (uint32_t)__cvta_generic_to_shared(dst);
    asm volatile("cp.async.cg.shared.global [%0], [%1], 16;\n" :: "r"(d), "l"(src));
}
__device__ __forceinline__ void cp_commit() {
    asm volatile("cp.async.commit_group;\n" ::: "memory");
}
template <int N>
__device__ __forceinline__ void cp_wait() {
    asm volatile("cp.async.wait_group %0;\n" :: "n"(N) : "memory");
}
__device__ __forceinline__ void ldm_x4(uint32_t* r, const void* p) {
    uint32_t a = (uint32_t)__cvta_generic_to_shared(p);
    asm volatile("ldmatrix.sync.aligned.m8n8.x4.shared.b16 {%0,%1,%2,%3}, [%4];\n"
                 : "=r"(r[0]), "=r"(r[1]), "=r"(r[2]), "=r"(r[3]) : "r"(a));
}
__device__ __forceinline__ void ldm_x4t(uint32_t* r, const void* p) {
    uint32_t a = (uint32_t)__cvta_generic_to_shared(p);
    asm volatile("ldmatrix.sync.aligned.m8n8.x4.trans.shared.b16 {%0,%1,%2,%3}, [%4];\n"
                 : "=r"(r[0]), "=r"(r[1]), "=r"(r[2]), "=r"(r[3]) : "r"(a));
}
__device__ __forceinline__ void mma16816(float* c, const uint32_t* a, uint32_t b0, uint32_t b1) {
    asm volatile(
        "mma.sync.aligned.m16n8k16.row.col.f32.bf16.bf16.f32 "
        "{%0,%1,%2,%3},{%4,%5,%6,%7},{%8,%9},{%0,%1,%2,%3};\n"
        : "+f"(c[0]), "+f"(c[1]), "+f"(c[2]), "+f"(c[3])
        : "r"(a[0]), "r"(a[1]), "r"(a[2]), "r"(a[3]), "r"(b0), "r"(b1));
}
__device__ __forceinline__ uint32_t packbf2(float a, float b) {
    __nv_bfloat162 t = __floats2bfloat162_rn(a, b);
    return *(uint32_t*)&t;
}

// ---------------- fat prep kernel (all independent elementwise prep in one launch) ----------
#define N_WC  (2048 * 352)   // Wc as float4 items (KQM/4 = 352)
#define N_WFM (2048 * 352)
#define N_G2  (1024 * 1024 / 4)
#define N_WV  (1024 * 1152 / 4)
#define N_W1T (8 * 1152 * 128)
#define PREP_TOTAL (N_WC + N_WFM + N_G2 + N_WV + N_W1T)   // 3,178,496

__global__ void __launch_bounds__(256)
prep_fat_k(const float* __restrict__ w, const float* __restrict__ Et,
           const float* __restrict__ fC, const float* __restrict__ W1,
           const float* __restrict__ W2, const float* __restrict__ Wv,
           const float* __restrict__ Wf, const float* __restrict__ beta,
           const float* __restrict__ g1w, const float* __restrict__ g2w,
           __nv_bfloat16* __restrict__ Wc, __nv_bfloat16* __restrict__ wfm,
           __nv_bfloat16* __restrict__ W1t, __nv_bfloat16* __restrict__ Wvb,
           __nv_bfloat16* __restrict__ g2wb) {
    int i = blockIdx.x * 256 + threadIdx.x;
    if (i < N_WC) {
        // Wc[2048][1408]: rows 0-1023 = [W2 | beta*Wf | 0]; rows 1024-2047 = [g1w_D | 0 | g1w_De]
        int row = i / 352, j = i - row * 352;
        float4 f = make_float4(0.f, 0.f, 0.f, 0.f);
        float sc = 1.f;
        if (row < 1024) {
            if (j < 256)      f = ((const float4*)W2)[(size_t)row * 256 + j];
            else if (j < 320) { f = ((const float4*)Wf)[(size_t)row * 64 + (j - 256)]; sc = beta[0]; }
        } else {
            int p = row - 1024;
            if (j < 256)      f = ((const float4*)g1w)[(size_t)p * 288 + j];
            else if (j >= 320) f = ((const float4*)g1w)[(size_t)p * 288 + 256 + (j - 320)];
        }
        __nv_bfloat162* o = (__nv_bfloat162*)(Wc + (size_t)row * KQM + j * 4);
        o[0] = __floats2bfloat162_rn(f.x * sc, f.y * sc);
        o[1] = __floats2bfloat162_rn(f.z * sc, f.w * sc);
        return;
    }
    i -= N_WC;
    if (i < N_WFM) {
        // wfm[2048][1408] = [w | fC | mean_kt(Et)]
        int c = i / 352, j = i - c * 352;
        float4 f;
        if (j < 256)      f = ((const float4*)w)[(size_t)c * 256 + j];
        else if (j < 320) f = ((const float4*)fC)[(size_t)c * 64 + (j - 256)];
        else {
            float4 a = make_float4(0.f, 0.f, 0.f, 0.f);
            const float4* ep = (const float4*)Et + (size_t)c * 64 * 32 + (j - 320);
            #pragma unroll 8
            for (int kt = 0; kt < 64; kt++) {
                float4 e = ep[kt * 32];
                a.x += e.x; a.y += e.y; a.z += e.z; a.w += e.w;
            }
            f = make_float4(a.x * (1.f/64.f), a.y * (1.f/64.f), a.z * (1.f/64.f), a.w * (1.f/64.f));
        }
        __nv_bfloat162* o = (__nv_bfloat162*)(wfm + (size_t)c * KQM + j * 4);
        o[0] = __floats2bfloat162_rn(f.x, f.y);
        o[1] = __floats2bfloat162_rn(f.z, f.w);
        return;
    }
    i -= N_WFM;
    if (i < N_G2) {
        float4 f = ((const float4*)g2w)[i];
        __nv_bfloat162* o = (__nv_bfloat162*)(g2wb + (size_t)i * 4);
        o[0] = __floats2bfloat162_rn(f.x, f.y);
        o[1] = __floats2bfloat162_rn(f.z, f.w);
        return;
    }
    i -= N_G2;
    if (i < N_WV) {
        float4 f = ((const float4*)Wv)[i];
        __nv_bfloat162* o = (__nv_bfloat162*)(Wvb + (size_t)i * 4);
        o[0] = __floats2bfloat162_rn(f.x, f.y);
        o[1] = __floats2bfloat162_rn(f.z, f.w);
        return;
    }
    i -= N_WV;
    if (i < N_W1T) {
        int d = i & 127;
        int x = (i >> 7) % DX;
        int h = i / (DX * DHH);
        W1t[i] = __float2bfloat16(W1[(size_t)(h * DHH + d) * DX + x]);
    }
}

// ---------------- GEMM body: C[128,128] tile of A[M,K] @ B[N,K]^T ----------------
// modes: 0=QH (col<1024 plain bf16, else relu+g1b bf16); 1=plain bf16;
//        2=sigmoid(v+e1[col]) f32; 3=gate: e2[idx]+e1[idx]*v f32
__device__ __forceinline__ void gemm_body(
    int mode,
    __nv_bfloat16 (&sA)[2][128][40], __nv_bfloat16 (&sB)[2][128][40],
    const __nv_bfloat16* __restrict__ A, const __nv_bfloat16* __restrict__ B,
    void* __restrict__ Out,
    int lda, int ldb, int ldc, int K, int m0, int n0, int czoff,
    const float* __restrict__ e1, const float* __restrict__ e2)
{
    const int tid  = threadIdx.x;
    const int lane = tid & 31, warp = tid >> 5;
    const int wm = (warp >> 1) << 5;
    const int wn = (warp & 1) << 6;

    float acc[2][8][4];
    #pragma unroll
    for (int i = 0; i < 2; i++)
        #pragma unroll
        for (int j = 0; j < 8; j++)
            #pragma unroll
            for (int r = 0; r < 4; r++) acc[i][j][r] = 0.f;

    auto tile_load = [&](int buf, int kt) {
        #pragma unroll
        for (int r = 0; r < 2; r++) {
            int id  = tid + (r << 8);
            int row = id >> 2;
            int cc  = (id & 3) << 3;
            cpasync16(&sA[buf][row][cc], A + (size_t)(m0 + row) * lda + kt + cc);
            cpasync16(&sB[buf][row][cc], B + (size_t)(n0 + row) * ldb + kt + cc);
        }
    };

    tile_load(0, 0);
    cp_commit();
    const int nk = K >> 5;
    for (int t = 0; t < nk; t++) {
        if (t + 1 < nk) {
            tile_load((t + 1) & 1, (t + 1) << 5);
            cp_commit();
            cp_wait<1>();
        } else {
            cp_wait<0>();
        }
        __syncthreads();
        const int buf = t & 1;
        #pragma unroll
        for (int s = 0; s < 2; s++) {
            uint32_t af[2][4], bfr[4][4];
            #pragma unroll
            for (int i = 0; i < 2; i++)
                ldm_x4(af[i], &sA[buf][wm + (i << 4) + (lane & 15)][(s << 4) + ((lane >> 4) << 3)]);
            #pragma unroll
            for (int j = 0; j < 4; j++)
                ldm_x4(bfr[j], &sB[buf][wn + (j << 4) + (lane & 15)][(s << 4) + ((lane >> 4) << 3)]);
            #pragma unroll
            for (int i = 0; i < 2; i++)
                #pragma unroll
                for (int j = 0; j < 4; j++) {
                    mma16816(acc[i][2 * j],     af[i], bfr[j][0], bfr[j][2]);
                    mma16816(acc[i][2 * j + 1], af[i], bfr[j][1], bfr[j][3]);
                }
        }
        __syncthreads();
    }

    #pragma unroll
    for (int i = 0; i < 2; i++) {
        #pragma unroll
        for (int j = 0; j < 8; j++) {
            const int colg = n0 + wn + (j << 3) + ((lane & 3) << 1);
            #pragma unroll
            for (int r2 = 0; r2 < 2; r2++) {
                const int row = m0 + wm + (i << 4) + (lane >> 2) + (r2 << 3);
                float v0 = acc[i][j][r2 * 2], v1 = acc[i][j][r2 * 2 + 1];
                const size_t oidx = (size_t)row * ldc + czoff + colg;
                if (mode == 0) {
                    if (colg >= 1024) {
                        v0 = fmaxf(v0 + e1[colg - 1024], 0.f);
                        v1 = fmaxf(v1 + e1[colg - 1023], 0.f);
                    }
                    *(__nv_bfloat162*)((__nv_bfloat16*)Out + oidx) =
                        __floats2bfloat162_rn(v0, v1);
                } else if (mode == 1) {
                    *(__nv_bfloat162*)((__nv_bfloat16*)Out + oidx) =
                        __floats2bfloat162_rn(v0, v1);
                } else if (mode == 2) {
                    v0 = 1.f / (1.f + __expf(-(v0 + e1[colg])));
                    v1 = 1.f / (1.f + __expf(-(v1 + e1[colg + 1])));
                    *(float2*)((float*)Out + oidx) = make_float2(v0, v1);
                } else { // gate: U = w + g*v
                    v0 = e2[oidx] + e1[oidx] * v0;
                    v1 = e2[oidx + 1] + e1[oidx + 1] * v1;
                    *(float2*)((float*)Out + oidx) = make_float2(v0, v1);
                }
            }
        }
    }
}

// QH = wfm @ Wc^T  (Q cols 0-1023 plain; hmid cols 1024-2047 relu+g1b)
__global__ void __launch_bounds__(256)
gemm_qh_k(const __nv_bfloat16* __restrict__ wfm, const __nv_bfloat16* __restrict__ Wc,
          __nv_bfloat16* __restrict__ QH, const float* __restrict__ g1b) {
    __shared__ __align__(16) __nv_bfloat16 sA[2][128][40];
    __shared__ __align__(16) __nv_bfloat16 sB[2][128][40];
    gemm_body(0, sA, sB, wfm, Wc, QH, KQM, KQM, 2048, KQM,
              blockIdx.y << 7, blockIdx.x << 7, 0, g1b, nullptr);
}

// fat: blocks [0,1152) -> qt[:,h,:] = Q_h @ W1_h ; blocks [1152,1280) -> g = sigmoid(hmid@g2w^T+g2b)
__global__ void __launch_bounds__(256)
gemm_fat_k(const __nv_bfloat16* __restrict__ QH, const __nv_bfloat16* __restrict__ W1t,
           __nv_bfloat16* __restrict__ qt, const __nv_bfloat16* __restrict__ g2wb,
           float* __restrict__ gbuf, const float* __restrict__ g2b) {
    __shared__ __align__(16) __nv_bfloat16 sA[2][128][40];
    __shared__ __align__(16) __nv_bfloat16 sB[2][128][40];
    int bid = blockIdx.x;
    if (bid < 1152) {
        int bz = bid / 144, r = bid - bz * 144;
        int by = r / 9, bx = r - by * 9;
        gemm_body(1, sA, sB, QH + bz * 128, W1t + (size_t)bz * DX * DHH, qt,
                  2048, DHH, NH * DX, DHH, by << 7, bx << 7, bz * DX,
                  nullptr, nullptr);
    } else {
        int b2 = bid - 1152;
        int by = b2 >> 3, bx = b2 & 7;
        gemm_body(2, sA, sB, QH + 1024, g2wb, gbuf,
                  2048, PHH, DD, PHH, by << 7, bx << 7, 0, g2b, nullptr);
    }
}

// U = w + g * (Z @ Wv^T)  (batched per head)
__global__ void __launch_bounds__(256)
gemm_gate_k(const __nv_bfloat16* __restrict__ Z, const __nv_bfloat16* __restrict__ Wvb,
            float* __restrict__ U, const float* __restrict__ gbuf,
            const float* __restrict__ w) {
    __shared__ __align__(16) __nv_bfloat16 sA[2][128][40];
    __shared__ __align__(16) __nv_bfloat16 sB[2][128][40];
    gemm_body(3, sA, sB, Z + blockIdx.z * DX, Wvb + (size_t)blockIdx.z * DHH * DX, U,
              NH * DX, DX, DD, DX, blockIdx.y << 7, 0, blockIdx.z * DHH,
              gbuf, w);
}

// ---------------- fused per-c attention core (mma.sync) ----------------
#define FPW 580
#define SM_FP 0
#define SM_QT (64 * FPW)              // 37120
#define SM_SC (SM_QT + 8 * FPW)       // 41760
#define SM_AT (SM_SC + 512)           // 42272
#define ATTN_SMEM ((SM_AT + 576) * 4) // 171392 bytes

__global__ void __launch_bounds__(256, 1)
attn_fused_k(const float* __restrict__ F, const float* __restrict__ Et,
             const __nv_bfloat16* __restrict__ qtg, __nv_bfloat16* __restrict__ Z) {
    extern __shared__ uint32_t smem_u[];
    uint32_t* fp_s = smem_u + SM_FP;
    uint32_t* qt_s = smem_u + SM_QT;
    float*    sc_s = (float*)(smem_u + SM_SC);
    __nv_bfloat16* at_s = (__nv_bfloat16*)(smem_u + SM_AT);

    const int c = blockIdx.x;
    const int tid = threadIdx.x;
    const int wid = tid >> 5, lane = tid & 31;

    for (int i = tid; i < 64 * 288; i += 256) {
        int row = i / 288, j = i - row * 288;
        float4 v = (j < 256)
            ? ((const float4*)F)[((size_t)c * 64 + row) * 256 + j]
            : ((const float4*)Et)[((size_t)c * 64 + row) * 32 + (j - 256)];
        uint2 pk;
        pk.x = packbf2(v.x, v.y);
        pk.y = packbf2(v.z, v.w);
        *(uint2*)(fp_s + row * FPW + j * 2) = pk;
    }
    for (int i = tid; i < 8 * 288; i += 256) {
        int row = i / 288, j = i - row * 288;
        uint2 v = ((const uint2*)(qtg + (size_t)c * (NH * DX) + row * DX))[j];
        *(uint2*)(qt_s + row * FPW + j * 2) = v;
    }
    __syncthreads();

    // phase 1: scores[64,8] = Fp @ qt^T
    if (wid < 4) {
        const char* aP = (const char*)fp_s + (wid * 16 + (lane & 15)) * 2320 + (lane >> 4) * 16;
        const char* bP = (const char*)qt_s + (lane & 7) * 2320 + (lane >> 4) * 16;
        float cacc[4] = {0.f, 0.f, 0.f, 0.f};
        #pragma unroll 8
        for (int kk = 0; kk < 72; kk++) {
            uint32_t a[4], b[4];
            ldm_x4(a, aP + kk * 32);
            ldm_x4(b, bP + kk * 32);
            mma16816(cacc, a, b[0], b[2]);
        }
        const int kr = wid * 16 + (lane >> 2);
        const int h0 = (lane & 3) << 1;
        sc_s[h0 * 64 + kr]           = cacc[0];
        sc_s[(h0 + 1) * 64 + kr]     = cacc[1];
        sc_s[h0 * 64 + kr + 8]       = cacc[2];
        sc_s[(h0 + 1) * 64 + kr + 8] = cacc[3];
    } else {
        uint32_t* zp = (uint32_t*)(at_s + 8 * 72);
        for (int i = tid - 128; i < 288; i += 128) zp[i] = 0;
    }
    __syncthreads();

    // phase 2: softmax per head
    {
        const float sc = 0.08838834764831845f;
        float v0 = sc_s[wid * 64 + lane] * sc, v1 = sc_s[wid * 64 + lane + 32] * sc;
        float m = fmaxf(v0, v1);
        #pragma unroll
        for (int o = 16; o; o >>= 1) m = fmaxf(m, __shfl_xor_sync(0xffffffffu, m, o));
        float e0 = __expf(v0 - m), e1 = __expf(v1 - m);
        float s = e0 + e1;
        #pragma unroll
        for (int o = 16; o; o >>= 1) s += __shfl_xor_sync(0xffffffffu, s, o);
        float inv = 1.f / s;
        at_s[wid * 72 + lane]      = __float2bfloat16(e0 * inv);
        at_s[wid * 72 + lane + 32] = __float2bfloat16(e1 * inv);
    }
    __syncthreads();

    // phase 3: z[8,1152] = attn @ Fp
    {
        uint32_t afr[4][4];
        const char* aP = (const char*)at_s + (lane & 15) * 144 + (lane >> 4) * 16;
        #pragma unroll
        for (int kk = 0; kk < 4; kk++) ldm_x4(afr[kk], aP + kk * 32);

        const int brow = (lane & 7) + ((lane >> 3) & 1) * 8;
        const int bcol = (lane >> 4) * 8;
        #pragma unroll
        for (int xt = 0; xt < 9; xt++) {
            const int x0 = (wid * 9 + xt) * 16;
            const char* bP = (const char*)fp_s + brow * 2320 + (x0 + bcol) * 2;
            float c0[4] = {0.f, 0.f, 0.f, 0.f}, c1[4] = {0.f, 0.f, 0.f, 0.f};
            #pragma unroll
            for (int kk = 0; kk < 4; kk++) {
                uint32_t b[4];
                ldm_x4t(b, bP + kk * 16 * 2320);
                mma16816(c0, afr[kk], b[0], b[1]);
                mma16816(c1, afr[kk], b[2], b[3]);
            }
            const int h = lane >> 2, xo = (lane & 3);
            uint32_t* zo = (uint32_t*)(Z + (size_t)c * (NH * DX) + h * DX + x0);
            zo[xo]     = packbf2(c0[0], c0[1]);
            zo[xo + 4] = packbf2(c1[0], c1[1]);
        }
    }
}

// ---------------- finalize: out = U / max(||U||, eps) ----------------
__global__ void __launch_bounds__(256)
finalize_k(const float* __restrict__ U, float* __restrict__ out) {
    const int c = blockIdx.x, tid = threadIdx.x;
    const int wid = tid >> 5, lane = tid & 31;
    __shared__ float sred[8];
    float u[4]; float ss = 0.f;
    #pragma unroll
    for (int i = 0; i < 4; i++) {
        u[i] = U[(size_t)c * DD + i * 256 + tid];
        ss += u[i] * u[i];
    }
    #pragma unroll
    for (int o = 16; o; o >>= 1) ss += __shfl_xor_sync(0xffffffffu, ss, o);
    if (lane == 0) sred[wid] = ss;
    __syncthreads();
    float tot = 0.f;
    #pragma unroll
    for (int h = 0; h < 8; h++) tot += sred[h];
    float inv = 1.f / fmaxf(sqrtf(tot), 1e-12f);
    #pragma unroll
    for (int i = 0; i < 4; i++)
        out[(size_t)c * DD + i * 256 + tid] = u[i] * inv;
}

// ---------------- launch ----------------
extern "C" void kernel_launch(void* const* d_in, const int* in_sizes, int n_in,
                              void* d_out, int out_size) {
    const float* w   = (const float*)d_in[0];
    const float* F   = (const float*)d_in[1];
    const float* Et  = (const float*)d_in[2];
    const float* fC  = (const float*)d_in[3];
    const float* W1  = (const float*)d_in[4];
    const float* W2  = (const float*)d_in[5];
    const float* Wv  = (const float*)d_in[6];
    const float* Wf  = (const float*)d_in[7];
    // alpha (d_in[8]) cancels in softmax — unused
    const float* beta = (const float*)d_in[9];
    const float* g1w = (const float*)d_in[10];
    const float* g1b = (const float*)d_in[11];
    const float* g2w = (const float*)d_in[12];
    const float* g2b = (const float*)d_in[13];
    float* out = (float*)d_out;

    __nv_bfloat16 *Wc, *wfm, *QH, *W1t, *Wvb, *g2wb, *qt, *Z;
    float *gbuf, *U;
    cudaGetSymbolAddress((void**)&Wc,   g_Wc);
    cudaGetSymbolAddress((void**)&wfm,  g_wfm);
    cudaGetSymbolAddress((void**)&QH,   g_QH);
    cudaGetSymbolAddress((void**)&W1t,  g_W1t);
    cudaGetSymbolAddress((void**)&Wvb,  g_Wvb);
    cudaGetSymbolAddress((void**)&g2wb, g_g2wb);
    cudaGetSymbolAddress((void**)&qt,   g_qt);
    cudaGetSymbolAddress((void**)&Z,    g_Z);
    cudaGetSymbolAddress((void**)&gbuf, g_g);
    cudaGetSymbolAddress((void**)&U,    g_U);

    cudaFuncSetAttribute(attn_fused_k, cudaFuncAttributeMaxDynamicSharedMemorySize, ATTN_SMEM);

    // 1. all prep in one launch
    prep_fat_k<<<PREP_TOTAL / 256, 256>>>(w, Et, fC, W1, W2, Wv, Wf, beta, g1w, g2w,
                                          Wc, wfm, W1t, Wvb, g2wb);
    // 2. merged Q + gate1 GEMM: QH = wfm @ Wc^T
    gemm_qh_k<<<dim3(16, 16), 256>>>(wfm, Wc, QH, g1b);
    // 3. fat: qt (per-head) + g (sigmoid gate)
    gemm_fat_k<<<1280, 256>>>(QH, W1t, qt, g2wb, gbuf, g2b);
    // 4. fused attention core
    attn_fused_k<<<CC, 256, ATTN_SMEM>>>(F, Et, qt, Z);
    // 5. U = w + g * (Z @ Wv^T)
    gemm_gate_k<<<dim3(1, 16, 8), 256>>>(Z, Wvb, U, gbuf, w);
    // 6. normalize
    finalize_k<<<CC, 256>>>(U, out);
}

// round 7
// speedup vs baseline: 6.5913x; 1.2456x over previous
#include <cuda_runtime.h>
#include <cuda_bf16.h>
#include <cstdint>

// ---------------- problem dims ----------------
#define CC   2048
#define KTT  64
#define DD   1024
#define DE   128
#define DF   256
#define NH   8
#define DHH  128
#define DX   1152   // D + De
#define PHH  1024
#define KQM  1408   // D + Df + De  (merged Q/gate1 GEMM K)

// ---------------- scratch (__device__ globals; no allocations) ----------------
__device__ __align__(128) __nv_bfloat16 g_Wc[2048 * KQM];        // [W2|b*Wf|0 ; g1w_D|0|g1w_De]
__device__ __align__(128) __nv_bfloat16 g_wfm[CC * KQM];         // [w | fC | mean(Et)]
__device__ __align__(128) __nv_bfloat16 g_QH[CC * 2048];         // [Q | hmid]
__device__ __align__(128) __nv_bfloat16 g_W1t[NH * DX * DHH];    // [h][x][d]
__device__ __align__(128) __nv_bfloat16 g_Wvb[DD * DX];
__device__ __align__(128) __nv_bfloat16 g_g2wb[DD * PHH];
__device__ __align__(128) __nv_bfloat16 g_qt[(size_t)CC * NH * DX];
__device__ __align__(128) __nv_bfloat16 g_Z[(size_t)CC * NH * DX];
__device__ __align__(128) float g_g[CC * DD];
__device__ __align__(128) float g_U[CC * DD];

// ---------------- PTX helpers ----------------
__device__ __forceinline__ void cpasync16(void* dst, const void* src) {
    uint32_t d = (uint32_t)__cvta_generic_to_shared(dst);
    asm volatile("cp.async.cg.shared.global [%0], [%1], 16;\n" :: "r"(d), "l"(src));
}
__device__ __forceinline__ void cp_commit() {
    asm volatile("cp.async.commit_group;\n" ::: "memory");
}
template <int N>
__device__ __forceinline__ void cp_wait() {
    asm volatile("cp.async.wait_group %0;\n" :: "n"(N) : "memory");
}
__device__ __forceinline__ void ldm_x4(uint32_t* r, const void* p) {
    uint32_t a = (uint32_t)__cvta_generic_to_shared(p);
    asm volatile("ldmatrix.sync.aligned.m8n8.x4.shared.b16 {%0,%1,%2,%3}, [%4];\n"
                 : "=r"(r[0]), "=r"(r[1]), "=r"(r[2]), "=r"(r[3]) : "r"(a));
}
__device__ __forceinline__ void ldm_x4t(uint32_t* r, const void* p) {
    uint32_t a = (uint32_t)__cvta_generic_to_shared(p);
    asm volatile("ldmatrix.sync.aligned.m8n8.x4.trans.shared.b16 {%0,%1,%2,%3}, [%4];\n"
                 : "=r"(r[0]), "=r"(r[1]), "=r"(r[2]), "=r"(r[3]) : "r"(a));
}
__device__ __forceinline__ void mma16816(float* c, const uint32_t* a, uint32_t b0, uint32_t b1) {
    asm volatile(
        "mma.sync.aligned.m16n8k16.row.col.f32.bf16.bf16.f32 "
        "{%0,%1,%2,%3},{%4,%5,%6,%7},{%8,%9},{%0,%1,%2,%3};\n"
        : "+f"(c[0]), "+f"(c[1]), "+f"(c[2]), "+f"(c[3])
        : "r"(a[0]), "r"(a[1]), "r"(a[2]), "r"(a[3]), "r"(b0), "r"(b1));
}
__device__ __forceinline__ uint32_t packbf2(float a, float b) {
    __nv_bfloat162 t = __floats2bfloat162_rn(a, b);
    return *(uint32_t*)&t;
}

// ---------------- fat prep kernel ----------------
#define N_WC  (2048 * 352)
#define N_WFM (2048 * 352)
#define N_G2  (1024 * 1024 / 4)
#define N_WV  (1024 * 1152 / 4)
#define N_W1T (8 * 1152 * 128)
#define PREP_TOTAL (N_WC + N_WFM + N_G2 + N_WV + N_W1T)

__global__ void __launch_bounds__(256)
prep_fat_k(const float* __restrict__ w, const float* __restrict__ Et,
           const float* __restrict__ fC, const float* __restrict__ W1,
           const float* __restrict__ W2, const float* __restrict__ Wv,
           const float* __restrict__ Wf, const float* __restrict__ beta,
           const float* __restrict__ g1w, const float* __restrict__ g2w,
           __nv_bfloat16* __restrict__ Wc, __nv_bfloat16* __restrict__ wfm,
           __nv_bfloat16* __restrict__ W1t, __nv_bfloat16* __restrict__ Wvb,
           __nv_bfloat16* __restrict__ g2wb) {
    int i = blockIdx.x * 256 + threadIdx.x;
    if (i < N_WC) {
        int row = i / 352, j = i - row * 352;
        float4 f = make_float4(0.f, 0.f, 0.f, 0.f);
        float sc = 1.f;
        if (row < 1024) {
            if (j < 256)      f = ((const float4*)W2)[(size_t)row * 256 + j];
            else if (j < 320) { f = ((const float4*)Wf)[(size_t)row * 64 + (j - 256)]; sc = beta[0]; }
        } else {
            int p = row - 1024;
            if (j < 256)      f = ((const float4*)g1w)[(size_t)p * 288 + j];
            else if (j >= 320) f = ((const float4*)g1w)[(size_t)p * 288 + 256 + (j - 320)];
        }
        __nv_bfloat162* o = (__nv_bfloat162*)(Wc + (size_t)row * KQM + j * 4);
        o[0] = __floats2bfloat162_rn(f.x * sc, f.y * sc);
        o[1] = __floats2bfloat162_rn(f.z * sc, f.w * sc);
        return;
    }
    i -= N_WC;
    if (i < N_WFM) {
        int c = i / 352, j = i - c * 352;
        float4 f;
        if (j < 256)      f = ((const float4*)w)[(size_t)c * 256 + j];
        else if (j < 320) f = ((const float4*)fC)[(size_t)c * 64 + (j - 256)];
        else {
            float4 a = make_float4(0.f, 0.f, 0.f, 0.f);
            const float4* ep = (const float4*)Et + (size_t)c * 64 * 32 + (j - 320);
            #pragma unroll 8
            for (int kt = 0; kt < 64; kt++) {
                float4 e = ep[kt * 32];
                a.x += e.x; a.y += e.y; a.z += e.z; a.w += e.w;
            }
            f = make_float4(a.x * (1.f/64.f), a.y * (1.f/64.f), a.z * (1.f/64.f), a.w * (1.f/64.f));
        }
        __nv_bfloat162* o = (__nv_bfloat162*)(wfm + (size_t)c * KQM + j * 4);
        o[0] = __floats2bfloat162_rn(f.x, f.y);
        o[1] = __floats2bfloat162_rn(f.z, f.w);
        return;
    }
    i -= N_WFM;
    if (i < N_G2) {
        float4 f = ((const float4*)g2w)[i];
        __nv_bfloat162* o = (__nv_bfloat162*)(g2wb + (size_t)i * 4);
        o[0] = __floats2bfloat162_rn(f.x, f.y);
        o[1] = __floats2bfloat162_rn(f.z, f.w);
        return;
    }
    i -= N_G2;
    if (i < N_WV) {
        float4 f = ((const float4*)Wv)[i];
        __nv_bfloat162* o = (__nv_bfloat162*)(Wvb + (size_t)i * 4);
        o[0] = __floats2bfloat162_rn(f.x, f.y);
        o[1] = __floats2bfloat162_rn(f.z, f.w);
        return;
    }
    i -= N_WV;
    if (i < N_W1T) {
        int d = i & 127;
        int x = (i >> 7) % DX;
        int h = i / (DX * DHH);
        W1t[i] = __float2bfloat16(W1[(size_t)(h * DHH + d) * DX + x]);
    }
}

// ---------------- GEMM body (128x128 tile, A@B^T) ----------------
__device__ __forceinline__ void gemm_body(
    int mode,
    __nv_bfloat16 (&sA)[2][128][40], __nv_bfloat16 (&sB)[2][128][40],
    const __nv_bfloat16* __restrict__ A, const __nv_bfloat16* __restrict__ B,
    void* __restrict__ Out,
    int lda, int ldb, int ldc, int K, int m0, int n0, int czoff,
    const float* __restrict__ e1, const float* __restrict__ e2)
{
    const int tid  = threadIdx.x;
    const int lane = tid & 31, warp = tid >> 5;
    const int wm = (warp >> 1) << 5;
    const int wn = (warp & 1) << 6;

    float acc[2][8][4];
    #pragma unroll
    for (int i = 0; i < 2; i++)
        #pragma unroll
        for (int j = 0; j < 8; j++)
            #pragma unroll
            for (int r = 0; r < 4; r++) acc[i][j][r] = 0.f;

    auto tile_load = [&](int buf, int kt) {
        #pragma unroll
        for (int r = 0; r < 2; r++) {
            int id  = tid + (r << 8);
            int row = id >> 2;
            int cc  = (id & 3) << 3;
            cpasync16(&sA[buf][row][cc], A + (size_t)(m0 + row) * lda + kt + cc);
            cpasync16(&sB[buf][row][cc], B + (size_t)(n0 + row) * ldb + kt + cc);
        }
    };

    tile_load(0, 0);
    cp_commit();
    const int nk = K >> 5;
    for (int t = 0; t < nk; t++) {
        if (t + 1 < nk) {
            tile_load((t + 1) & 1, (t + 1) << 5);
            cp_commit();
            cp_wait<1>();
        } else {
            cp_wait<0>();
        }
        __syncthreads();
        const int buf = t & 1;
        #pragma unroll
        for (int s = 0; s < 2; s++) {
            uint32_t af[2][4], bfr[4][4];
            #pragma unroll
            for (int i = 0; i < 2; i++)
                ldm_x4(af[i], &sA[buf][wm + (i << 4) + (lane & 15)][(s << 4) + ((lane >> 4) << 3)]);
            #pragma unroll
            for (int j = 0; j < 4; j++)
                ldm_x4(bfr[j], &sB[buf][wn + (j << 4) + (lane & 15)][(s << 4) + ((lane >> 4) << 3)]);
            #pragma unroll
            for (int i = 0; i < 2; i++)
                #pragma unroll
                for (int j = 0; j < 4; j++) {
                    mma16816(acc[i][2 * j],     af[i], bfr[j][0], bfr[j][2]);
                    mma16816(acc[i][2 * j + 1], af[i], bfr[j][1], bfr[j][3]);
                }
        }
        __syncthreads();
    }

    #pragma unroll
    for (int i = 0; i < 2; i++) {
        #pragma unroll
        for (int j = 0; j < 8; j++) {
            const int colg = n0 + wn + (j << 3) + ((lane & 3) << 1);
            #pragma unroll
            for (int r2 = 0; r2 < 2; r2++) {
                const int row = m0 + wm + (i << 4) + (lane >> 2) + (r2 << 3);
                float v0 = acc[i][j][r2 * 2], v1 = acc[i][j][r2 * 2 + 1];
                const size_t oidx = (size_t)row * ldc + czoff + colg;
                if (mode == 0) {
                    if (colg >= 1024) {
                        v0 = fmaxf(v0 + e1[colg - 1024], 0.f);
                        v1 = fmaxf(v1 + e1[colg - 1023], 0.f);
                    }
                    *(__nv_bfloat162*)((__nv_bfloat16*)Out + oidx) =
                        __floats2bfloat162_rn(v0, v1);
                } else if (mode == 1) {
                    *(__nv_bfloat162*)((__nv_bfloat16*)Out + oidx) =
                        __floats2bfloat162_rn(v0, v1);
                } else if (mode == 2) {
                    v0 = 1.f / (1.f + __expf(-(v0 + e1[colg])));
                    v1 = 1.f / (1.f + __expf(-(v1 + e1[colg + 1])));
                    *(float2*)((float*)Out + oidx) = make_float2(v0, v1);
                } else { // gate: U = w + g*v
                    v0 = e2[oidx] + e1[oidx] * v0;
                    v1 = e2[oidx + 1] + e1[oidx + 1] * v1;
                    *(float2*)((float*)Out + oidx) = make_float2(v0, v1);
                }
            }
        }
    }
}

__global__ void __launch_bounds__(256)
gemm_qh_k(const __nv_bfloat16* __restrict__ wfm, const __nv_bfloat16* __restrict__ Wc,
          __nv_bfloat16* __restrict__ QH, const float* __restrict__ g1b) {
    __shared__ __align__(16) __nv_bfloat16 sA[2][128][40];
    __shared__ __align__(16) __nv_bfloat16 sB[2][128][40];
    gemm_body(0, sA, sB, wfm, Wc, QH, KQM, KQM, 2048, KQM,
              blockIdx.y << 7, blockIdx.x << 7, 0, g1b, nullptr);
}

__global__ void __launch_bounds__(256)
gemm_fat_k(const __nv_bfloat16* __restrict__ QH, const __nv_bfloat16* __restrict__ W1t,
           __nv_bfloat16* __restrict__ qt, const __nv_bfloat16* __restrict__ g2wb,
           float* __restrict__ gbuf, const float* __restrict__ g2b) {
    __shared__ __align__(16) __nv_bfloat16 sA[2][128][40];
    __shared__ __align__(16) __nv_bfloat16 sB[2][128][40];
    int bid = blockIdx.x;
    if (bid < 1152) {
        int bz = bid / 144, r = bid - bz * 144;
        int by = r / 9, bx = r - by * 9;
        gemm_body(1, sA, sB, QH + bz * 128, W1t + (size_t)bz * DX * DHH, qt,
                  2048, DHH, NH * DX, DHH, by << 7, bx << 7, bz * DX,
                  nullptr, nullptr);
    } else {
        int b2 = bid - 1152;
        int by = b2 >> 3, bx = b2 & 7;
        gemm_body(2, sA, sB, QH + 1024, g2wb, gbuf,
                  2048, PHH, DD, PHH, by << 7, bx << 7, 0, g2b, nullptr);
    }
}

__global__ void __launch_bounds__(256)
gemm_gate_k(const __nv_bfloat16* __restrict__ Z, const __nv_bfloat16* __restrict__ Wvb,
            float* __restrict__ U, const float* __restrict__ gbuf,
            const float* __restrict__ w) {
    __shared__ __align__(16) __nv_bfloat16 sA[2][128][40];
    __shared__ __align__(16) __nv_bfloat16 sB[2][128][40];
    gemm_body(3, sA, sB, Z + blockIdx.z * DX, Wvb + (size_t)blockIdx.z * DHH * DX, U,
              NH * DX, DX, DD, DX, blockIdx.y << 7, 0, blockIdx.z * DHH,
              gbuf, w);
}

// ---------------- fused per-c attention core: 512 threads, K-split phase 1 ----------------
// smem (u32 idx): Fp[64][1160 bf16]; qt[8][1160 bf16]; partial scores f32 [4][8][64];
// attn bf16 [16][72]
#define FPW 580
#define SM_FP 0
#define SM_QT (64 * FPW)               // 37120
#define SM_SC (SM_QT + 8 * FPW)        // 41760 (4 parts x 512 f32 = 2048)
#define SM_AT (SM_SC + 2048)           // 43808
#define ATTN_SMEM ((SM_AT + 576) * 4)  // 177536 bytes

__global__ void __launch_bounds__(512, 1)
attn_fused_k(const float* __restrict__ F, const float* __restrict__ Et,
             const __nv_bfloat16* __restrict__ qtg, __nv_bfloat16* __restrict__ Z) {
    extern __shared__ uint32_t smem_u[];
    uint32_t* fp_s = smem_u + SM_FP;
    uint32_t* qt_s = smem_u + SM_QT;
    float*    sc_s = (float*)(smem_u + SM_SC);
    __nv_bfloat16* at_s = (__nv_bfloat16*)(smem_u + SM_AT);

    const int c = blockIdx.x;
    const int tid = threadIdx.x;
    const int wid = tid >> 5, lane = tid & 31;

    // ---- load F|Et -> bf16 smem (64 x 1152), qt (8 x 1152); zero attn pad rows ----
    for (int i = tid; i < 64 * 288; i += 512) {
        int row = i / 288, j = i - row * 288;
        float4 v = (j < 256)
            ? ((const float4*)F)[((size_t)c * 64 + row) * 256 + j]
            : ((const float4*)Et)[((size_t)c * 64 + row) * 32 + (j - 256)];
        uint2 pk;
        pk.x = packbf2(v.x, v.y);
        pk.y = packbf2(v.z, v.w);
        *(uint2*)(fp_s + row * FPW + j * 2) = pk;
    }
    for (int i = tid; i < 8 * 288; i += 512) {
        int row = i / 288, j = i - row * 288;
        uint2 v = ((const uint2*)(qtg + (size_t)c * (NH * DX) + row * DX))[j];
        *(uint2*)(qt_s + row * FPW + j * 2) = v;
    }
    if (tid < 288) ((uint32_t*)(at_s + 8 * 72))[tid] = 0;   // pad rows 8-15
    __syncthreads();

    // ---- phase 1: scores[64,8] = Fp @ qt^T ; 16 warps = 4 tiles x 4 K-parts ----
    {
        const int t = wid & 3;          // score row tile (16 rows)
        const int p = wid >> 2;         // K part (18 k-steps = 288 x-cols)
        const char* aP = (const char*)fp_s + (t * 16 + (lane & 15)) * 2320
                         + (lane >> 4) * 16 + p * 576;
        const char* bP = (const char*)qt_s + (lane & 7) * 2320
                         + (lane >> 4) * 16 + p * 576;
        float cacc[4] = {0.f, 0.f, 0.f, 0.f};
        #pragma unroll 6
        for (int kk = 0; kk < 18; kk++) {
            uint32_t a[4], b[4];
            ldm_x4(a, aP + kk * 32);
            ldm_x4(b, bP + kk * 32);
            mma16816(cacc, a, b[0], b[2]);
        }
        const int kr = t * 16 + (lane >> 2);
        const int h0 = (lane & 3) << 1;
        float* ps = sc_s + p * 512;
        ps[h0 * 64 + kr]           = cacc[0];
        ps[(h0 + 1) * 64 + kr]     = cacc[1];
        ps[h0 * 64 + kr + 8]       = cacc[2];
        ps[(h0 + 1) * 64 + kr + 8] = cacc[3];
    }
    __syncthreads();

    // ---- phase 2: reduce K-parts + softmax per head (warps 0-7) ----
    if (wid < 8) {
        const float sc = 0.08838834764831845f;
        float v0 = 0.f, v1 = 0.f;
        #pragma unroll
        for (int p = 0; p < 4; p++) {
            v0 += sc_s[p * 512 + wid * 64 + lane];
            v1 += sc_s[p * 512 + wid * 64 + lane + 32];
        }
        v0 *= sc; v1 *= sc;
        float m = fmaxf(v0, v1);
        #pragma unroll
        for (int o = 16; o; o >>= 1) m = fmaxf(m, __shfl_xor_sync(0xffffffffu, m, o));
        float e0 = __expf(v0 - m), e1 = __expf(v1 - m);
        float s = e0 + e1;
        #pragma unroll
        for (int o = 16; o; o >>= 1) s += __shfl_xor_sync(0xffffffffu, s, o);
        float inv = 1.f / s;
        at_s[wid * 72 + lane]      = __float2bfloat16(e0 * inv);
        at_s[wid * 72 + lane + 32] = __float2bfloat16(e1 * inv);
    }
    __syncthreads();

    // ---- phase 3: z[8,1152] = attn @ Fp ; 16 warps stride over 72 x-tiles ----
    {
        uint32_t afr[4][4];
        const char* aP = (const char*)at_s + (lane & 15) * 144 + (lane >> 4) * 16;
        #pragma unroll
        for (int kk = 0; kk < 4; kk++) ldm_x4(afr[kk], aP + kk * 32);

        const int brow = (lane & 7) + ((lane >> 3) & 1) * 8;
        const int bcol = (lane >> 4) * 8;
        for (int xt = wid; xt < 72; xt += 16) {
            const int x0 = xt * 16;
            const char* bP = (const char*)fp_s + brow * 2320 + (x0 + bcol) * 2;
            float c0[4] = {0.f, 0.f, 0.f, 0.f}, c1[4] = {0.f, 0.f, 0.f, 0.f};
            #pragma unroll
            for (int kk = 0; kk < 4; kk++) {
                uint32_t b[4];
                ldm_x4t(b, bP + kk * 16 * 2320);
                mma16816(c0, afr[kk], b[0], b[1]);
                mma16816(c1, afr[kk], b[2], b[3]);
            }
            const int h = lane >> 2, xo = (lane & 3);
            uint32_t* zo = (uint32_t*)(Z + (size_t)c * (NH * DX) + h * DX + x0);
            zo[xo]     = packbf2(c0[0], c0[1]);
            zo[xo + 4] = packbf2(c1[0], c1[1]);
        }
    }
}

// ---------------- finalize: out = U / max(||U||, eps) ----------------
__global__ void __launch_bounds__(256)
finalize_k(const float* __restrict__ U, float* __restrict__ out) {
    const int c = blockIdx.x, tid = threadIdx.x;
    const int wid = tid >> 5, lane = tid & 31;
    __shared__ float sred[8];
    float u[4]; float ss = 0.f;
    #pragma unroll
    for (int i = 0; i < 4; i++) {
        u[i] = U[(size_t)c * DD + i * 256 + tid];
        ss += u[i] * u[i];
    }
    #pragma unroll
    for (int o = 16; o; o >>= 1) ss += __shfl_xor_sync(0xffffffffu, ss, o);
    if (lane == 0) sred[wid] = ss;
    __syncthreads();
    float tot = 0.f;
    #pragma unroll
    for (int h = 0; h < 8; h++) tot += sred[h];
    float inv = 1.f / fmaxf(sqrtf(tot), 1e-12f);
    #pragma unroll
    for (int i = 0; i < 4; i++)
        out[(size_t)c * DD + i * 256 + tid] = u[i] * inv;
}

// ---------------- launch ----------------
extern "C" void kernel_launch(void* const* d_in, const int* in_sizes, int n_in,
                              void* d_out, int out_size) {
    const float* w   = (const float*)d_in[0];
    const float* F   = (const float*)d_in[1];
    const float* Et  = (const float*)d_in[2];
    const float* fC  = (const float*)d_in[3];
    const float* W1  = (const float*)d_in[4];
    const float* W2  = (const float*)d_in[5];
    const float* Wv  = (const float*)d_in[6];
    const float* Wf  = (const float*)d_in[7];
    // alpha (d_in[8]) cancels in softmax — unused
    const float* beta = (const float*)d_in[9];
    const float* g1w = (const float*)d_in[10];
    const float* g1b = (const float*)d_in[11];
    const float* g2w = (const float*)d_in[12];
    const float* g2b = (const float*)d_in[13];
    float* out = (float*)d_out;

    __nv_bfloat16 *Wc, *wfm, *QH, *W1t, *Wvb, *g2wb, *qt, *Z;
    float *gbuf, *U;
    cudaGetSymbolAddress((void**)&Wc,   g_Wc);
    cudaGetSymbolAddress((void**)&wfm,  g_wfm);
    cudaGetSymbolAddress((void**)&QH,   g_QH);
    cudaGetSymbolAddress((void**)&W1t,  g_W1t);
    cudaGetSymbolAddress((void**)&Wvb,  g_Wvb);
    cudaGetSymbolAddress((void**)&g2wb, g_g2wb);
    cudaGetSymbolAddress((void**)&qt,   g_qt);
    cudaGetSymbolAddress((void**)&Z,    g_Z);
    cudaGetSymbolAddress((void**)&gbuf, g_g);
    cudaGetSymbolAddress((void**)&U,    g_U);

    cudaFuncSetAttribute(attn_fused_k, cudaFuncAttributeMaxDynamicSharedMemorySize, ATTN_SMEM);

    prep_fat_k<<<PREP_TOTAL / 256, 256>>>(w, Et, fC, W1, W2, Wv, Wf, beta, g1w, g2w,
                                          Wc, wfm, W1t, Wvb, g2wb);
    gemm_qh_k<<<dim3(16, 16), 256>>>(wfm, Wc, QH, g1b);
    gemm_fat_k<<<1280, 256>>>(QH, W1t, qt, g2wb, gbuf, g2b);
    attn_fused_k<<<CC, 512, ATTN_SMEM>>>(F, Et, qt, Z);
    gemm_gate_k<<<dim3(1, 16, 8), 256>>>(Z, Wvb, U, gbuf, w);
    finalize_k<<<CC, 256>>>(U, out);
}

// round 8
// speedup vs baseline: 7.1804x; 1.0894x over previous
#include <cuda_runtime.h>
#include <cuda_bf16.h>
#include <cstdint>

// ---------------- problem dims ----------------
#define CC   2048
#define KTT  64
#define DD   1024
#define DE   128
#define DF   256
#define NH   8
#define DHH  128
#define DX   1152   // D + De
#define PHH  1024
#define KQM  1408   // D + Df + De  (merged Q/gate1 GEMM K)

// ---------------- scratch (__device__ globals; no allocations) ----------------
__device__ __align__(128) __nv_bfloat16 g_Wc[2048 * KQM];        // [W2|b*Wf|0 ; g1w_D|0|g1w_De]
__device__ __align__(128) __nv_bfloat16 g_wfm[CC * KQM];         // [w | fC | mean(Et)]
__device__ __align__(128) __nv_bfloat16 g_QH[CC * 2048];         // [Q | hmid]
__device__ __align__(128) __nv_bfloat16 g_W1t[NH * DX * DHH];    // [h][x][d]
__device__ __align__(128) __nv_bfloat16 g_Wvb[DD * DX];
__device__ __align__(128) __nv_bfloat16 g_g2wb[DD * PHH];
__device__ __align__(128) __nv_bfloat16 g_qt[(size_t)CC * NH * DX];
__device__ __align__(128) __nv_bfloat16 g_Z[(size_t)CC * NH * DX];
__device__ __align__(128) float g_g[CC * DD];
__device__ __align__(128) float g_U[CC * DD];

// ---------------- PTX helpers ----------------
__device__ __forceinline__ void cpasync16(void* dst, const void* src) {
    uint32_t d = (uint32_t)__cvta_generic_to_shared(dst);
    asm volatile("cp.async.cg.shared.global [%0], [%1], 16;\n" :: "r"(d), "l"(src));
}
__device__ __forceinline__ void cp_commit() {
    asm volatile("cp.async.commit_group;\n" ::: "memory");
}
template <int N>
__device__ __forceinline__ void cp_wait() {
    asm volatile("cp.async.wait_group %0;\n" :: "n"(N) : "memory");
}
__device__ __forceinline__ void ldm_x4(uint32_t* r, const void* p) {
    uint32_t a = (uint32_t)__cvta_generic_to_shared(p);
    asm volatile("ldmatrix.sync.aligned.m8n8.x4.shared.b16 {%0,%1,%2,%3}, [%4];\n"
                 : "=r"(r[0]), "=r"(r[1]), "=r"(r[2]), "=r"(r[3]) : "r"(a));
}
__device__ __forceinline__ void ldm_x4t(uint32_t* r, const void* p) {
    uint32_t a = (uint32_t)__cvta_generic_to_shared(p);
    asm volatile("ldmatrix.sync.aligned.m8n8.x4.trans.shared.b16 {%0,%1,%2,%3}, [%4];\n"
                 : "=r"(r[0]), "=r"(r[1]), "=r"(r[2]), "=r"(r[3]) : "r"(a));
}
__device__ __forceinline__ void mma16816(float* c, const uint32_t* a, uint32_t b0, uint32_t b1) {
    asm volatile(
        "mma.sync.aligned.m16n8k16.row.col.f32.bf16.bf16.f32 "
        "{%0,%1,%2,%3},{%4,%5,%6,%7},{%8,%9},{%0,%1,%2,%3};\n"
        : "+f"(c[0]), "+f"(c[1]), "+f"(c[2]), "+f"(c[3])
        : "r"(a[0]), "r"(a[1]), "r"(a[2]), "r"(a[3]), "r"(b0), "r"(b1));
}
__device__ __forceinline__ uint32_t packbf2(float a, float b) {
    __nv_bfloat162 t = __floats2bfloat162_rn(a, b);
    return *(uint32_t*)&t;
}

// ---------------- fat prep kernel ----------------
#define N_WC  (2048 * 352)
#define N_WFM (2048 * 352)
#define N_G2  (1024 * 1024 / 4)
#define N_WV  (1024 * 1152 / 4)
#define N_W1T (8 * 1152 * 128)
#define PREP_TOTAL (N_WC + N_WFM + N_G2 + N_WV + N_W1T)

__global__ void __launch_bounds__(256)
prep_fat_k(const float* __restrict__ w, const float* __restrict__ Et,
           const float* __restrict__ fC, const float* __restrict__ W1,
           const float* __restrict__ W2, const float* __restrict__ Wv,
           const float* __restrict__ Wf, const float* __restrict__ beta,
           const float* __restrict__ g1w, const float* __restrict__ g2w,
           __nv_bfloat16* __restrict__ Wc, __nv_bfloat16* __restrict__ wfm,
           __nv_bfloat16* __restrict__ W1t, __nv_bfloat16* __restrict__ Wvb,
           __nv_bfloat16* __restrict__ g2wb) {
    int i = blockIdx.x * 256 + threadIdx.x;
    if (i < N_WC) {
        int row = i / 352, j = i - row * 352;
        float4 f = make_float4(0.f, 0.f, 0.f, 0.f);
        float sc = 1.f;
        if (row < 1024) {
            if (j < 256)      f = ((const float4*)W2)[(size_t)row * 256 + j];
            else if (j < 320) { f = ((const float4*)Wf)[(size_t)row * 64 + (j - 256)]; sc = beta[0]; }
        } else {
            int p = row - 1024;
            if (j < 256)      f = ((const float4*)g1w)[(size_t)p * 288 + j];
            else if (j >= 320) f = ((const float4*)g1w)[(size_t)p * 288 + 256 + (j - 320)];
        }
        __nv_bfloat162* o = (__nv_bfloat162*)(Wc + (size_t)row * KQM + j * 4);
        o[0] = __floats2bfloat162_rn(f.x * sc, f.y * sc);
        o[1] = __floats2bfloat162_rn(f.z * sc, f.w * sc);
        return;
    }
    i -= N_WC;
    if (i < N_WFM) {
        int c = i / 352, j = i - c * 352;
        float4 f;
        if (j < 256)      f = ((const float4*)w)[(size_t)c * 256 + j];
        else if (j < 320) f = ((const float4*)fC)[(size_t)c * 64 + (j - 256)];
        else {
            float4 a = make_float4(0.f, 0.f, 0.f, 0.f);
            const float4* ep = (const float4*)Et + (size_t)c * 64 * 32 + (j - 320);
            #pragma unroll 8
            for (int kt = 0; kt < 64; kt++) {
                float4 e = ep[kt * 32];
                a.x += e.x; a.y += e.y; a.z += e.z; a.w += e.w;
            }
            f = make_float4(a.x * (1.f/64.f), a.y * (1.f/64.f), a.z * (1.f/64.f), a.w * (1.f/64.f));
        }
        __nv_bfloat162* o = (__nv_bfloat162*)(wfm + (size_t)c * KQM + j * 4);
        o[0] = __floats2bfloat162_rn(f.x, f.y);
        o[1] = __floats2bfloat162_rn(f.z, f.w);
        return;
    }
    i -= N_WFM;
    if (i < N_G2) {
        float4 f = ((const float4*)g2w)[i];
        __nv_bfloat162* o = (__nv_bfloat162*)(g2wb + (size_t)i * 4);
        o[0] = __floats2bfloat162_rn(f.x, f.y);
        o[1] = __floats2bfloat162_rn(f.z, f.w);
        return;
    }
    i -= N_G2;
    if (i < N_WV) {
        float4 f = ((const float4*)Wv)[i];
        __nv_bfloat162* o = (__nv_bfloat162*)(Wvb + (size_t)i * 4);
        o[0] = __floats2bfloat162_rn(f.x, f.y);
        o[1] = __floats2bfloat162_rn(f.z, f.w);
        return;
    }
    i -= N_WV;
    if (i < N_W1T) {
        int d = i & 127;
        int x = (i >> 7) % DX;
        int h = i / (DX * DHH);
        W1t[i] = __float2bfloat16(W1[(size_t)(h * DHH + d) * DX + x]);
    }
}

// ---------------- GEMM body (128x128 tile, A@B^T) ----------------
__device__ __forceinline__ void gemm_body(
    int mode,
    __nv_bfloat16 (&sA)[2][128][40], __nv_bfloat16 (&sB)[2][128][40],
    const __nv_bfloat16* __restrict__ A, const __nv_bfloat16* __restrict__ B,
    void* __restrict__ Out,
    int lda, int ldb, int ldc, int K, int m0, int n0, int czoff,
    const float* __restrict__ e1, const float* __restrict__ e2)
{
    const int tid  = threadIdx.x;
    const int lane = tid & 31, warp = tid >> 5;
    const int wm = (warp >> 1) << 5;
    const int wn = (warp & 1) << 6;

    float acc[2][8][4];
    #pragma unroll
    for (int i = 0; i < 2; i++)
        #pragma unroll
        for (int j = 0; j < 8; j++)
            #pragma unroll
            for (int r = 0; r < 4; r++) acc[i][j][r] = 0.f;

    auto tile_load = [&](int buf, int kt) {
        #pragma unroll
        for (int r = 0; r < 2; r++) {
            int id  = tid + (r << 8);
            int row = id >> 2;
            int cc  = (id & 3) << 3;
            cpasync16(&sA[buf][row][cc], A + (size_t)(m0 + row) * lda + kt + cc);
            cpasync16(&sB[buf][row][cc], B + (size_t)(n0 + row) * ldb + kt + cc);
        }
    };

    tile_load(0, 0);
    cp_commit();
    const int nk = K >> 5;
    for (int t = 0; t < nk; t++) {
        if (t + 1 < nk) {
            tile_load((t + 1) & 1, (t + 1) << 5);
            cp_commit();
            cp_wait<1>();
        } else {
            cp_wait<0>();
        }
        __syncthreads();
        const int buf = t & 1;
        #pragma unroll
        for (int s = 0; s < 2; s++) {
            uint32_t af[2][4], bfr[4][4];
            #pragma unroll
            for (int i = 0; i < 2; i++)
                ldm_x4(af[i], &sA[buf][wm + (i << 4) + (lane & 15)][(s << 4) + ((lane >> 4) << 3)]);
            #pragma unroll
            for (int j = 0; j < 4; j++)
                ldm_x4(bfr[j], &sB[buf][wn + (j << 4) + (lane & 15)][(s << 4) + ((lane >> 4) << 3)]);
            #pragma unroll
            for (int i = 0; i < 2; i++)
                #pragma unroll
                for (int j = 0; j < 4; j++) {
                    mma16816(acc[i][2 * j],     af[i], bfr[j][0], bfr[j][2]);
                    mma16816(acc[i][2 * j + 1], af[i], bfr[j][1], bfr[j][3]);
                }
        }
        __syncthreads();
    }

    #pragma unroll
    for (int i = 0; i < 2; i++) {
        #pragma unroll
        for (int j = 0; j < 8; j++) {
            const int colg = n0 + wn + (j << 3) + ((lane & 3) << 1);
            #pragma unroll
            for (int r2 = 0; r2 < 2; r2++) {
                const int row = m0 + wm + (i << 4) + (lane >> 2) + (r2 << 3);
                float v0 = acc[i][j][r2 * 2], v1 = acc[i][j][r2 * 2 + 1];
                const size_t oidx = (size_t)row * ldc + czoff + colg;
                if (mode == 0) {
                    if (colg >= 1024) {
                        v0 = fmaxf(v0 + e1[colg - 1024], 0.f);
                        v1 = fmaxf(v1 + e1[colg - 1023], 0.f);
                    }
                    *(__nv_bfloat162*)((__nv_bfloat16*)Out + oidx) =
                        __floats2bfloat162_rn(v0, v1);
                } else if (mode == 1) {
                    *(__nv_bfloat162*)((__nv_bfloat16*)Out + oidx) =
                        __floats2bfloat162_rn(v0, v1);
                } else if (mode == 2) {
                    v0 = 1.f / (1.f + __expf(-(v0 + e1[colg])));
                    v1 = 1.f / (1.f + __expf(-(v1 + e1[colg + 1])));
                    *(float2*)((float*)Out + oidx) = make_float2(v0, v1);
                } else { // gate: U = w + g*v
                    v0 = e2[oidx] + e1[oidx] * v0;
                    v1 = e2[oidx + 1] + e1[oidx + 1] * v1;
                    *(float2*)((float*)Out + oidx) = make_float2(v0, v1);
                }
            }
        }
    }
}

__global__ void __launch_bounds__(256)
gemm_qh_k(const __nv_bfloat16* __restrict__ wfm, const __nv_bfloat16* __restrict__ Wc,
          __nv_bfloat16* __restrict__ QH, const float* __restrict__ g1b) {
    __shared__ __align__(16) __nv_bfloat16 sA[2][128][40];
    __shared__ __align__(16) __nv_bfloat16 sB[2][128][40];
    gemm_body(0, sA, sB, wfm, Wc, QH, KQM, KQM, 2048, KQM,
              blockIdx.y << 7, blockIdx.x << 7, 0, g1b, nullptr);
}

__global__ void __launch_bounds__(256)
gemm_fat_k(const __nv_bfloat16* __restrict__ QH, const __nv_bfloat16* __restrict__ W1t,
           __nv_bfloat16* __restrict__ qt, const __nv_bfloat16* __restrict__ g2wb,
           float* __restrict__ gbuf, const float* __restrict__ g2b) {
    __shared__ __align__(16) __nv_bfloat16 sA[2][128][40];
    __shared__ __align__(16) __nv_bfloat16 sB[2][128][40];
    int bid = blockIdx.x;
    if (bid < 1152) {
        int bz = bid / 144, r = bid - bz * 144;
        int by = r / 9, bx = r - by * 9;
        gemm_body(1, sA, sB, QH + bz * 128, W1t + (size_t)bz * DX * DHH, qt,
                  2048, DHH, NH * DX, DHH, by << 7, bx << 7, bz * DX,
                  nullptr, nullptr);
    } else {
        int b2 = bid - 1152;
        int by = b2 >> 3, bx = b2 & 7;
        gemm_body(2, sA, sB, QH + 1024, g2wb, gbuf,
                  2048, PHH, DD, PHH, by << 7, bx << 7, 0, g2b, nullptr);
    }
}

__global__ void __launch_bounds__(256)
gemm_gate_k(const __nv_bfloat16* __restrict__ Z, const __nv_bfloat16* __restrict__ Wvb,
            float* __restrict__ U, const float* __restrict__ gbuf,
            const float* __restrict__ w) {
    __shared__ __align__(16) __nv_bfloat16 sA[2][128][40];
    __shared__ __align__(16) __nv_bfloat16 sB[2][128][40];
    gemm_body(3, sA, sB, Z + blockIdx.z * DX, Wvb + (size_t)blockIdx.z * DHH * DX, U,
              NH * DX, DX, DD, DX, blockIdx.y << 7, 0, blockIdx.z * DHH,
              gbuf, w);
}

// ---------------- fused per-c attention core: 1024 threads, 32 warps ----------------
// smem (u32 idx): Fp[64][1160 bf16]; qt[8][1160 bf16]; partial scores f32 [8][8][64];
// attn bf16 [16][72]
#define FPW 580
#define SM_FP 0
#define SM_QT (64 * FPW)               // 37120
#define SM_SC (SM_QT + 8 * FPW)        // 41760 (8 parts x 512 f32 = 4096)
#define SM_AT (SM_SC + 4096)           // 45856
#define ATTN_SMEM ((SM_AT + 576) * 4)  // 185728 bytes

__global__ void __launch_bounds__(1024, 1)
attn_fused_k(const float* __restrict__ F, const float* __restrict__ Et,
             const __nv_bfloat16* __restrict__ qtg, __nv_bfloat16* __restrict__ Z) {
    extern __shared__ uint32_t smem_u[];
    uint32_t* fp_s = smem_u + SM_FP;
    uint32_t* qt_s = smem_u + SM_QT;
    float*    sc_s = (float*)(smem_u + SM_SC);
    __nv_bfloat16* at_s = (__nv_bfloat16*)(smem_u + SM_AT);

    const int c = blockIdx.x;
    const int tid = threadIdx.x;
    const int wid = tid >> 5, lane = tid & 31;

    // ---- load F|Et -> bf16 smem (64 x 1152), qt (8 x 1152); zero attn pad rows ----
    #pragma unroll 4
    for (int i = tid; i < 64 * 288; i += 1024) {
        int row = i / 288, j = i - row * 288;
        float4 v = (j < 256)
            ? ((const float4*)F)[((size_t)c * 64 + row) * 256 + j]
            : ((const float4*)Et)[((size_t)c * 64 + row) * 32 + (j - 256)];
        uint2 pk;
        pk.x = packbf2(v.x, v.y);
        pk.y = packbf2(v.z, v.w);
        *(uint2*)(fp_s + row * FPW + j * 2) = pk;
    }
    for (int i = tid; i < 8 * 288; i += 1024) {
        int row = i / 288, j = i - row * 288;
        uint2 v = ((const uint2*)(qtg + (size_t)c * (NH * DX) + row * DX))[j];
        *(uint2*)(qt_s + row * FPW + j * 2) = v;
    }
    if (tid < 288) ((uint32_t*)(at_s + 8 * 72))[tid] = 0;   // pad rows 8-15
    __syncthreads();

    // ---- phase 1: scores[64,8] = Fp @ qt^T ; 32 warps = 4 row-tiles x 8 K-parts ----
    {
        const int t = wid & 3;          // score row tile (16 rows)
        const int p = wid >> 2;         // K part (9 k-steps = 144 x-cols)
        const char* aP = (const char*)fp_s + (t * 16 + (lane & 15)) * 2320
                         + (lane >> 4) * 16 + p * 288;
        const char* bP = (const char*)qt_s + (lane & 7) * 2320
                         + (lane >> 4) * 16 + p * 288;
        float cacc[4] = {0.f, 0.f, 0.f, 0.f};
        #pragma unroll 3
        for (int kk = 0; kk < 9; kk++) {
            uint32_t a[4], b[4];
            ldm_x4(a, aP + kk * 32);
            ldm_x4(b, bP + kk * 32);
            mma16816(cacc, a, b[0], b[2]);
        }
        const int kr = t * 16 + (lane >> 2);
        const int h0 = (lane & 3) << 1;
        float* ps = sc_s + p * 512;
        ps[h0 * 64 + kr]           = cacc[0];
        ps[(h0 + 1) * 64 + kr]     = cacc[1];
        ps[h0 * 64 + kr + 8]       = cacc[2];
        ps[(h0 + 1) * 64 + kr + 8] = cacc[3];
    }
    __syncthreads();

    // ---- phase 2: reduce 8 K-parts + softmax per head (warps 0-7) ----
    if (wid < 8) {
        const float sc = 0.08838834764831845f;
        float v0 = 0.f, v1 = 0.f;
        #pragma unroll
        for (int p = 0; p < 8; p++) {
            v0 += sc_s[p * 512 + wid * 64 + lane];
            v1 += sc_s[p * 512 + wid * 64 + lane + 32];
        }
        v0 *= sc; v1 *= sc;
        float m = fmaxf(v0, v1);
        #pragma unroll
        for (int o = 16; o; o >>= 1) m = fmaxf(m, __shfl_xor_sync(0xffffffffu, m, o));
        float e0 = __expf(v0 - m), e1 = __expf(v1 - m);
        float s = e0 + e1;
        #pragma unroll
        for (int o = 16; o; o >>= 1) s += __shfl_xor_sync(0xffffffffu, s, o);
        float inv = 1.f / s;
        at_s[wid * 72 + lane]      = __float2bfloat16(e0 * inv);
        at_s[wid * 72 + lane + 32] = __float2bfloat16(e1 * inv);
    }
    __syncthreads();

    // ---- phase 3: z[8,1152] = attn @ Fp ; 32 warps stride over 72 x-tiles ----
    {
        uint32_t afr[4][4];
        const char* aP = (const char*)at_s + (lane & 15) * 144 + (lane >> 4) * 16;
        #pragma unroll
        for (int kk = 0; kk < 4; kk++) ldm_x4(afr[kk], aP + kk * 32);

        const int brow = (lane & 7) + ((lane >> 3) & 1) * 8;
        const int bcol = (lane >> 4) * 8;
        for (int xt = wid; xt < 72; xt += 32) {
            const int x0 = xt * 16;
            const char* bP = (const char*)fp_s + brow * 2320 + (x0 + bcol) * 2;
            float c0[4] = {0.f, 0.f, 0.f, 0.f}, c1[4] = {0.f, 0.f, 0.f, 0.f};
            #pragma unroll
            for (int kk = 0; kk < 4; kk++) {
                uint32_t b[4];
                ldm_x4t(b, bP + kk * 16 * 2320);
                mma16816(c0, afr[kk], b[0], b[1]);
                mma16816(c1, afr[kk], b[2], b[3]);
            }
            const int h = lane >> 2, xo = (lane & 3);
            uint32_t* zo = (uint32_t*)(Z + (size_t)c * (NH * DX) + h * DX + x0);
            zo[xo]     = packbf2(c0[0], c0[1]);
            zo[xo + 4] = packbf2(c1[0], c1[1]);
        }
    }
}

// ---------------- finalize: out = U / max(||U||, eps) ----------------
__global__ void __launch_bounds__(256)
finalize_k(const float* __restrict__ U, float* __restrict__ out) {
    const int c = blockIdx.x, tid = threadIdx.x;
    const int wid = tid >> 5, lane = tid & 31;
    __shared__ float sred[8];
    float u[4]; float ss = 0.f;
    #pragma unroll
    for (int i = 0; i < 4; i++) {
        u[i] = U[(size_t)c * DD + i * 256 + tid];
        ss += u[i] * u[i];
    }
    #pragma unroll
    for (int o = 16; o; o >>= 1) ss += __shfl_xor_sync(0xffffffffu, ss, o);
    if (lane == 0) sred[wid] = ss;
    __syncthreads();
    float tot = 0.f;
    #pragma unroll
    for (int h = 0; h < 8; h++) tot += sred[h];
    float inv = 1.f / fmaxf(sqrtf(tot), 1e-12f);
    #pragma unroll
    for (int i = 0; i < 4; i++)
        out[(size_t)c * DD + i * 256 + tid] = u[i] * inv;
}

// ---------------- launch ----------------
extern "C" void kernel_launch(void* const* d_in, const int* in_sizes, int n_in,
                              void* d_out, int out_size) {
    const float* w   = (const float*)d_in[0];
    const float* F   = (const float*)d_in[1];
    const float* Et  = (const float*)d_in[2];
    const float* fC  = (const float*)d_in[3];
    const float* W1  = (const float*)d_in[4];
    const float* W2  = (const float*)d_in[5];
    const float* Wv  = (const float*)d_in[6];
    const float* Wf  = (const float*)d_in[7];
    // alpha (d_in[8]) cancels in softmax — unused
    const float* beta = (const float*)d_in[9];
    const float* g1w = (const float*)d_in[10];
    const float* g1b = (const float*)d_in[11];
    const float* g2w = (const float*)d_in[12];
    const float* g2b = (const float*)d_in[13];
    float* out = (float*)d_out;

    __nv_bfloat16 *Wc, *wfm, *QH, *W1t, *Wvb, *g2wb, *qt, *Z;
    float *gbuf, *U;
    cudaGetSymbolAddress((void**)&Wc,   g_Wc);
    cudaGetSymbolAddress((void**)&wfm,  g_wfm);
    cudaGetSymbolAddress((void**)&QH,   g_QH);
    cudaGetSymbolAddress((void**)&W1t,  g_W1t);
    cudaGetSymbolAddress((void**)&Wvb,  g_Wvb);
    cudaGetSymbolAddress((void**)&g2wb, g_g2wb);
    cudaGetSymbolAddress((void**)&qt,   g_qt);
    cudaGetSymbolAddress((void**)&Z,    g_Z);
    cudaGetSymbolAddress((void**)&gbuf, g_g);
    cudaGetSymbolAddress((void**)&U,    g_U);

    cudaFuncSetAttribute(attn_fused_k, cudaFuncAttributeMaxDynamicSharedMemorySize, ATTN_SMEM);

    prep_fat_k<<<PREP_TOTAL / 256, 256>>>(w, Et, fC, W1, W2, Wv, Wf, beta, g1w, g2w,
                                          Wc, wfm, W1t, Wvb, g2wb);
    gemm_qh_k<<<dim3(16, 16), 256>>>(wfm, Wc, QH, g1b);
    gemm_fat_k<<<1280, 256>>>(QH, W1t, qt, g2wb, gbuf, g2b);
    attn_fused_k<<<CC, 1024, ATTN_SMEM>>>(F, Et, qt, Z);
    gemm_gate_k<<<dim3(1, 16, 8), 256>>>(Z, Wvb, U, gbuf, w);
    finalize_k<<<CC, 256>>>(U, out);
}

// round 9
// speedup vs baseline: 8.0054x; 1.1149x over previous
#include <cuda_runtime.h>
#include <cuda_bf16.h>
#include <cstdint>

// ---------------- problem dims ----------------
#define CC   2048
#define KTT  64
#define DD   1024
#define DE   128
#define DF   256
#define NH   8
#define DHH  128
#define DX   1152   // D + De
#define PHH  1024
#define KQM  1408   // D + Df + De  (merged Q/gate1 GEMM K)

// ---------------- scratch (__device__ globals; no allocations) ----------------
__device__ __align__(128) __nv_bfloat16 g_Wc[2048 * KQM];        // [W2|b*Wf|0 ; g1w_D|0|g1w_De]
__device__ __align__(128) __nv_bfloat16 g_wfm[CC * KQM];         // [w | fC | mean(Et)]
__device__ __align__(128) __nv_bfloat16 g_QH[CC * 2048];         // [Q | hmid]
__device__ __align__(128) __nv_bfloat16 g_W1t[NH * DX * DHH];    // [h][x][d]
__device__ __align__(128) __nv_bfloat16 g_Wvb[DD * DX];
__device__ __align__(128) __nv_bfloat16 g_g2wb[DD * PHH];
__device__ __align__(128) __nv_bfloat16 g_qt[(size_t)CC * NH * DX];
__device__ __align__(128) __nv_bfloat16 g_Z[(size_t)CC * NH * DX];
__device__ __align__(128) float g_g[CC * DD];
__device__ __align__(128) float g_U[CC * DD];

// ---------------- PTX helpers ----------------
__device__ __forceinline__ void cpasync16(void* dst, const void* src) {
    uint32_t d = (uint32_t)__cvta_generic_to_shared(dst);
    asm volatile("cp.async.cg.shared.global [%0], [%1], 16;\n" :: "r"(d), "l"(src));
}
__device__ __forceinline__ void cp_commit() {
    asm volatile("cp.async.commit_group;\n" ::: "memory");
}
template <int N>
__device__ __forceinline__ void cp_wait() {
    asm volatile("cp.async.wait_group %0;\n" :: "n"(N) : "memory");
}
__device__ __forceinline__ void ldm_x4(uint32_t* r, const void* p) {
    uint32_t a = (uint32_t)__cvta_generic_to_shared(p);
    asm volatile("ldmatrix.sync.aligned.m8n8.x4.shared.b16 {%0,%1,%2,%3}, [%4];\n"
                 : "=r"(r[0]), "=r"(r[1]), "=r"(r[2]), "=r"(r[3]) : "r"(a));
}
__device__ __forceinline__ void ldm_x4t(uint32_t* r, const void* p) {
    uint32_t a = (uint32_t)__cvta_generic_to_shared(p);
    asm volatile("ldmatrix.sync.aligned.m8n8.x4.trans.shared.b16 {%0,%1,%2,%3}, [%4];\n"
                 : "=r"(r[0]), "=r"(r[1]), "=r"(r[2]), "=r"(r[3]) : "r"(a));
}
__device__ __forceinline__ void mma16816(float* c, const uint32_t* a, uint32_t b0, uint32_t b1) {
    asm volatile(
        "mma.sync.aligned.m16n8k16.row.col.f32.bf16.bf16.f32 "
        "{%0,%1,%2,%3},{%4,%5,%6,%7},{%8,%9},{%0,%1,%2,%3};\n"
        : "+f"(c[0]), "+f"(c[1]), "+f"(c[2]), "+f"(c[3])
        : "r"(a[0]), "r"(a[1]), "r"(a[2]), "r"(a[3]), "r"(b0), "r"(b1));
}
__device__ __forceinline__ uint32_t packbf2(float a, float b) {
    __nv_bfloat162 t = __floats2bfloat162_rn(a, b);
    return *(uint32_t*)&t;
}
__device__ __forceinline__ void prefetchL2(const void* p) {
    asm volatile("prefetch.global.L2 [%0];" :: "l"(p));
}

// ---------------- fat prep kernel ----------------
#define N_WC  (2048 * 352)
#define N_WFM (2048 * 352)
#define N_G2  (1024 * 1024 / 4)
#define N_WV  (1024 * 1152 / 4)
#define N_W1T (8 * 1152 * 128)
#define PREP_TOTAL (N_WC + N_WFM + N_G2 + N_WV + N_W1T)

__global__ void __launch_bounds__(256)
prep_fat_k(const float* __restrict__ w, const float* __restrict__ Et,
           const float* __restrict__ fC, const float* __restrict__ W1,
           const float* __restrict__ W2, const float* __restrict__ Wv,
           const float* __restrict__ Wf, const float* __restrict__ beta,
           const float* __restrict__ g1w, const float* __restrict__ g2w,
           __nv_bfloat16* __restrict__ Wc, __nv_bfloat16* __restrict__ wfm,
           __nv_bfloat16* __restrict__ W1t, __nv_bfloat16* __restrict__ Wvb,
           __nv_bfloat16* __restrict__ g2wb) {
    int i = blockIdx.x * 256 + threadIdx.x;
    if (i < N_WC) {
        int row = i / 352, j = i - row * 352;
        float4 f = make_float4(0.f, 0.f, 0.f, 0.f);
        float sc = 1.f;
        if (row < 1024) {
            if (j < 256)      f = ((const float4*)W2)[(size_t)row * 256 + j];
            else if (j < 320) { f = ((const float4*)Wf)[(size_t)row * 64 + (j - 256)]; sc = beta[0]; }
        } else {
            int p = row - 1024;
            if (j < 256)      f = ((const float4*)g1w)[(size_t)p * 288 + j];
            else if (j >= 320) f = ((const float4*)g1w)[(size_t)p * 288 + 256 + (j - 320)];
        }
        __nv_bfloat162* o = (__nv_bfloat162*)(Wc + (size_t)row * KQM + j * 4);
        o[0] = __floats2bfloat162_rn(f.x * sc, f.y * sc);
        o[1] = __floats2bfloat162_rn(f.z * sc, f.w * sc);
        return;
    }
    i -= N_WC;
    if (i < N_WFM) {
        int c = i / 352, j = i - c * 352;
        float4 f;
        if (j < 256)      f = ((const float4*)w)[(size_t)c * 256 + j];
        else if (j < 320) f = ((const float4*)fC)[(size_t)c * 64 + (j - 256)];
        else {
            float4 a = make_float4(0.f, 0.f, 0.f, 0.f);
            const float4* ep = (const float4*)Et + (size_t)c * 64 * 32 + (j - 320);
            #pragma unroll 8
            for (int kt = 0; kt < 64; kt++) {
                float4 e = ep[kt * 32];
                a.x += e.x; a.y += e.y; a.z += e.z; a.w += e.w;
            }
            f = make_float4(a.x * (1.f/64.f), a.y * (1.f/64.f), a.z * (1.f/64.f), a.w * (1.f/64.f));
        }
        __nv_bfloat162* o = (__nv_bfloat162*)(wfm + (size_t)c * KQM + j * 4);
        o[0] = __floats2bfloat162_rn(f.x, f.y);
        o[1] = __floats2bfloat162_rn(f.z, f.w);
        return;
    }
    i -= N_WFM;
    if (i < N_G2) {
        float4 f = ((const float4*)g2w)[i];
        __nv_bfloat162* o = (__nv_bfloat162*)(g2wb + (size_t)i * 4);
        o[0] = __floats2bfloat162_rn(f.x, f.y);
        o[1] = __floats2bfloat162_rn(f.z, f.w);
        return;
    }
    i -= N_G2;
    if (i < N_WV) {
        float4 f = ((const float4*)Wv)[i];
        __nv_bfloat162* o = (__nv_bfloat162*)(Wvb + (size_t)i * 4);
        o[0] = __floats2bfloat162_rn(f.x, f.y);
        o[1] = __floats2bfloat162_rn(f.z, f.w);
        return;
    }
    i -= N_WV;
    if (i < N_W1T) {
        int d = i & 127;
        int x = (i >> 7) % DX;
        int h = i / (DX * DHH);
        W1t[i] = __float2bfloat16(W1[(size_t)(h * DHH + d) * DX + x]);
    }
}

// ---------------- GEMM body (128x128 tile, A@B^T) ----------------
__device__ __forceinline__ void gemm_body(
    int mode,
    __nv_bfloat16 (&sA)[2][128][40], __nv_bfloat16 (&sB)[2][128][40],
    const __nv_bfloat16* __restrict__ A, const __nv_bfloat16* __restrict__ B,
    void* __restrict__ Out,
    int lda, int ldb, int ldc, int K, int m0, int n0, int czoff,
    const float* __restrict__ e1, const float* __restrict__ e2)
{
    const int tid  = threadIdx.x;
    const int lane = tid & 31, warp = tid >> 5;
    const int wm = (warp >> 1) << 5;
    const int wn = (warp & 1) << 6;

    float acc[2][8][4];
    #pragma unroll
    for (int i = 0; i < 2; i++)
        #pragma unroll
        for (int j = 0; j < 8; j++)
            #pragma unroll
            for (int r = 0; r < 4; r++) acc[i][j][r] = 0.f;

    auto tile_load = [&](int buf, int kt) {
        #pragma unroll
        for (int r = 0; r < 2; r++) {
            int id  = tid + (r << 8);
            int row = id >> 2;
            int cc  = (id & 3) << 3;
            cpasync16(&sA[buf][row][cc], A + (size_t)(m0 + row) * lda + kt + cc);
            cpasync16(&sB[buf][row][cc], B + (size_t)(n0 + row) * ldb + kt + cc);
        }
    };

    tile_load(0, 0);
    cp_commit();
    const int nk = K >> 5;
    for (int t = 0; t < nk; t++) {
        if (t + 1 < nk) {
            tile_load((t + 1) & 1, (t + 1) << 5);
            cp_commit();
            cp_wait<1>();
        } else {
            cp_wait<0>();
        }
        __syncthreads();
        const int buf = t & 1;
        #pragma unroll
        for (int s = 0; s < 2; s++) {
            uint32_t af[2][4], bfr[4][4];
            #pragma unroll
            for (int i = 0; i < 2; i++)
                ldm_x4(af[i], &sA[buf][wm + (i << 4) + (lane & 15)][(s << 4) + ((lane >> 4) << 3)]);
            #pragma unroll
            for (int j = 0; j < 4; j++)
                ldm_x4(bfr[j], &sB[buf][wn + (j << 4) + (lane & 15)][(s << 4) + ((lane >> 4) << 3)]);
            #pragma unroll
            for (int i = 0; i < 2; i++)
                #pragma unroll
                for (int j = 0; j < 4; j++) {
                    mma16816(acc[i][2 * j],     af[i], bfr[j][0], bfr[j][2]);
                    mma16816(acc[i][2 * j + 1], af[i], bfr[j][1], bfr[j][3]);
                }
        }
        __syncthreads();
    }

    #pragma unroll
    for (int i = 0; i < 2; i++) {
        #pragma unroll
        for (int j = 0; j < 8; j++) {
            const int colg = n0 + wn + (j << 3) + ((lane & 3) << 1);
            #pragma unroll
            for (int r2 = 0; r2 < 2; r2++) {
                const int row = m0 + wm + (i << 4) + (lane >> 2) + (r2 << 3);
                float v0 = acc[i][j][r2 * 2], v1 = acc[i][j][r2 * 2 + 1];
                const size_t oidx = (size_t)row * ldc + czoff + colg;
                if (mode == 0) {
                    if (colg >= 1024) {
                        v0 = fmaxf(v0 + e1[colg - 1024], 0.f);
                        v1 = fmaxf(v1 + e1[colg - 1023], 0.f);
                    }
                    *(__nv_bfloat162*)((__nv_bfloat16*)Out + oidx) =
                        __floats2bfloat162_rn(v0, v1);
                } else if (mode == 1) {
                    *(__nv_bfloat162*)((__nv_bfloat16*)Out + oidx) =
                        __floats2bfloat162_rn(v0, v1);
                } else if (mode == 2) {
                    v0 = 1.f / (1.f + __expf(-(v0 + e1[colg])));
                    v1 = 1.f / (1.f + __expf(-(v1 + e1[colg + 1])));
                    *(float2*)((float*)Out + oidx) = make_float2(v0, v1);
                } else { // gate: U = w + g*v
                    v0 = e2[oidx] + e1[oidx] * v0;
                    v1 = e2[oidx + 1] + e1[oidx + 1] * v1;
                    *(float2*)((float*)Out + oidx) = make_float2(v0, v1);
                }
            }
        }
    }
}

__global__ void __launch_bounds__(256)
gemm_qh_k(const __nv_bfloat16* __restrict__ wfm, const __nv_bfloat16* __restrict__ Wc,
          __nv_bfloat16* __restrict__ QH, const float* __restrict__ g1b) {
    __shared__ __align__(16) __nv_bfloat16 sA[2][128][40];
    __shared__ __align__(16) __nv_bfloat16 sB[2][128][40];
    gemm_body(0, sA, sB, wfm, Wc, QH, KQM, KQM, 2048, KQM,
              blockIdx.y << 7, blockIdx.x << 7, 0, g1b, nullptr);
}

__global__ void __launch_bounds__(256)
gemm_fat_k(const __nv_bfloat16* __restrict__ QH, const __nv_bfloat16* __restrict__ W1t,
           __nv_bfloat16* __restrict__ qt, const __nv_bfloat16* __restrict__ g2wb,
           float* __restrict__ gbuf, const float* __restrict__ g2b) {
    __shared__ __align__(16) __nv_bfloat16 sA[2][128][40];
    __shared__ __align__(16) __nv_bfloat16 sB[2][128][40];
    int bid = blockIdx.x;
    if (bid < 1152) {
        int bz = bid / 144, r = bid - bz * 144;
        int by = r / 9, bx = r - by * 9;
        gemm_body(1, sA, sB, QH + bz * 128, W1t + (size_t)bz * DX * DHH, qt,
                  2048, DHH, NH * DX, DHH, by << 7, bx << 7, bz * DX,
                  nullptr, nullptr);
    } else {
        int b2 = bid - 1152;
        int by = b2 >> 3, bx = b2 & 7;
        gemm_body(2, sA, sB, QH + 1024, g2wb, gbuf,
                  2048, PHH, DD, PHH, by << 7, bx << 7, 0, g2b, nullptr);
    }
}

__global__ void __launch_bounds__(256)
gemm_gate_k(const __nv_bfloat16* __restrict__ Z, const __nv_bfloat16* __restrict__ Wvb,
            float* __restrict__ U, const float* __restrict__ gbuf,
            const float* __restrict__ w) {
    __shared__ __align__(16) __nv_bfloat16 sA[2][128][40];
    __shared__ __align__(16) __nv_bfloat16 sB[2][128][40];
    gemm_body(3, sA, sB, Z + blockIdx.z * DX, Wvb + (size_t)blockIdx.z * DHH * DX, U,
              NH * DX, DX, DD, DX, blockIdx.y << 7, 0, blockIdx.z * DHH,
              gbuf, w);
}

// ---------------- fused attention core: 1024 threads, 2 c's per CTA + L2 prefetch ----------------
// smem (u32 idx): Fp[64][1160 bf16]; qt[8][1160 bf16]; partial scores f32 [8][8][64];
// attn bf16 [16][72]
#define FPW 580
#define SM_FP 0
#define SM_QT (64 * FPW)               // 37120
#define SM_SC (SM_QT + 8 * FPW)        // 41760 (8 parts x 512 f32 = 4096)
#define SM_AT (SM_SC + 4096)           // 45856
#define ATTN_SMEM ((SM_AT + 576) * 4)  // 185728 bytes

__global__ void __launch_bounds__(1024, 1)
attn_fused_k(const float* __restrict__ F, const float* __restrict__ Et,
             const __nv_bfloat16* __restrict__ qtg, __nv_bfloat16* __restrict__ Z) {
    extern __shared__ uint32_t smem_u[];
    uint32_t* fp_s = smem_u + SM_FP;
    uint32_t* qt_s = smem_u + SM_QT;
    float*    sc_s = (float*)(smem_u + SM_SC);
    __nv_bfloat16* at_s = (__nv_bfloat16*)(smem_u + SM_AT);

    const int tid = threadIdx.x;
    const int wid = tid >> 5, lane = tid & 31;

    if (tid < 288) ((uint32_t*)(at_s + 8 * 72))[tid] = 0;   // pad rows 8-15 (persist both iters)

    #pragma unroll 1
    for (int it = 0; it < 2; it++) {
        const int c = blockIdx.x + (it << 10);
        if (it) __syncthreads();   // protect smem reuse (phase 3 of prev iter reads fp_s/at_s)

        // ---- load F|Et -> bf16 smem: warp w owns rows 2w, 2w+1; no div/mod ----
        {
            #pragma unroll
            for (int rr = 0; rr < 2; rr++) {
                const int row = (wid << 1) + rr;
                const float4* fF = (const float4*)F  + ((size_t)c * 64 + row) * 256;
                const float4* fE = (const float4*)Et + ((size_t)c * 64 + row) * 32;
                uint32_t* dst = fp_s + row * FPW;
                #pragma unroll
                for (int k2 = 0; k2 < 9; k2++) {
                    const int j = lane + (k2 << 5);
                    float4 v = (j < 256) ? fF[j] : fE[j - 256];
                    uint2 pk;
                    pk.x = packbf2(v.x, v.y);
                    pk.y = packbf2(v.z, v.w);
                    *(uint2*)(dst + j * 2) = pk;
                }
            }
        }
        // ---- load qt[c] (8 x 288 float4-equiv uint2) ----
        for (int i = tid; i < 8 * 288; i += 1024) {
            int row = i / 288, j = i - row * 288;
            uint2 v = ((const uint2*)(qtg + (size_t)c * (NH * DX) + row * DX))[j];
            *(uint2*)(qt_s + row * FPW + j * 2) = v;
        }
        __syncthreads();

        // ---- prefetch next c's inputs into L2 during compute phases ----
        if (it == 0) {
            const int c2 = blockIdx.x + 1024;
            const char* pf = (const char*)(F + (size_t)c2 * 64 * 1024);      // 256 KB = 2048 lines
            #pragma unroll
            for (int r = 0; r < 2; r++) prefetchL2(pf + (tid + (r << 10)) * 128);
            const char* pe = (const char*)(Et + (size_t)c2 * 64 * 128);      // 32 KB = 256 lines
            if (tid < 256) prefetchL2(pe + tid * 128);
            const char* pq = (const char*)(qtg + (size_t)c2 * (NH * DX));    // 18 KB = 144 lines
            if (tid >= 256 && tid < 400) prefetchL2(pq + (tid - 256) * 128);
        }

        // ---- phase 1: scores[64,8] = Fp @ qt^T ; 32 warps = 4 row-tiles x 8 K-parts ----
        {
            const int t = wid & 3;
            const int p = wid >> 2;
            const char* aP = (const char*)fp_s + (t * 16 + (lane & 15)) * 2320
                             + (lane >> 4) * 16 + p * 288;
            const char* bP = (const char*)qt_s + (lane & 7) * 2320
                             + (lane >> 4) * 16 + p * 288;
            float cacc[4] = {0.f, 0.f, 0.f, 0.f};
            #pragma unroll 3
            for (int kk = 0; kk < 9; kk++) {
                uint32_t a[4], b[4];
                ldm_x4(a, aP + kk * 32);
                ldm_x4(b, bP + kk * 32);
                mma16816(cacc, a, b[0], b[2]);
            }
            const int kr = t * 16 + (lane >> 2);
            const int h0 = (lane & 3) << 1;
            float* ps = sc_s + p * 512;
            ps[h0 * 64 + kr]           = cacc[0];
            ps[(h0 + 1) * 64 + kr]     = cacc[1];
            ps[h0 * 64 + kr + 8]       = cacc[2];
            ps[(h0 + 1) * 64 + kr + 8] = cacc[3];
        }
        __syncthreads();

        // ---- phase 2: reduce 8 K-parts + softmax per head (warps 0-7) ----
        if (wid < 8) {
            const float sc = 0.08838834764831845f;
            float v0 = 0.f, v1 = 0.f;
            #pragma unroll
            for (int p = 0; p < 8; p++) {
                v0 += sc_s[p * 512 + wid * 64 + lane];
                v1 += sc_s[p * 512 + wid * 64 + lane + 32];
            }
            v0 *= sc; v1 *= sc;
            float m = fmaxf(v0, v1);
            #pragma unroll
            for (int o = 16; o; o >>= 1) m = fmaxf(m, __shfl_xor_sync(0xffffffffu, m, o));
            float e0 = __expf(v0 - m), e1 = __expf(v1 - m);
            float s = e0 + e1;
            #pragma unroll
            for (int o = 16; o; o >>= 1) s += __shfl_xor_sync(0xffffffffu, s, o);
            float inv = 1.f / s;
            at_s[wid * 72 + lane]      = __float2bfloat16(e0 * inv);
            at_s[wid * 72 + lane + 32] = __float2bfloat16(e1 * inv);
        }
        __syncthreads();

        // ---- phase 3: z[8,1152] = attn @ Fp ; 32 warps over 72 x-tiles ----
        {
            uint32_t afr[4][4];
            const char* aP = (const char*)at_s + (lane & 15) * 144 + (lane >> 4) * 16;
            #pragma unroll
            for (int kk = 0; kk < 4; kk++) ldm_x4(afr[kk], aP + kk * 32);

            const int brow = (lane & 7) + ((lane >> 3) & 1) * 8;
            const int bcol = (lane >> 4) * 8;
            for (int xt = wid; xt < 72; xt += 32) {
                const int x0 = xt * 16;
                const char* bP = (const char*)fp_s + brow * 2320 + (x0 + bcol) * 2;
                float c0[4] = {0.f, 0.f, 0.f, 0.f}, c1[4] = {0.f, 0.f, 0.f, 0.f};
                #pragma unroll
                for (int kk = 0; kk < 4; kk++) {
                    uint32_t b[4];
                    ldm_x4t(b, bP + kk * 16 * 2320);
                    mma16816(c0, afr[kk], b[0], b[1]);
                    mma16816(c1, afr[kk], b[2], b[3]);
                }
                const int h = lane >> 2, xo = (lane & 3);
                uint32_t* zo = (uint32_t*)(Z + (size_t)c * (NH * DX) + h * DX + x0);
                zo[xo]     = packbf2(c0[0], c0[1]);
                zo[xo + 4] = packbf2(c1[0], c1[1]);
            }
        }
    }
}

// ---------------- finalize: out = U / max(||U||, eps) ----------------
__global__ void __launch_bounds__(256)
finalize_k(const float* __restrict__ U, float* __restrict__ out) {
    const int c = blockIdx.x, tid = threadIdx.x;
    const int wid = tid >> 5, lane = tid & 31;
    __shared__ float sred[8];
    float u[4]; float ss = 0.f;
    #pragma unroll
    for (int i = 0; i < 4; i++) {
        u[i] = U[(size_t)c * DD + i * 256 + tid];
        ss += u[i] * u[i];
    }
    #pragma unroll
    for (int o = 16; o; o >>= 1) ss += __shfl_xor_sync(0xffffffffu, ss, o);
    if (lane == 0) sred[wid] = ss;
    __syncthreads();
    float tot = 0.f;
    #pragma unroll
    for (int h = 0; h < 8; h++) tot += sred[h];
    float inv = 1.f / fmaxf(sqrtf(tot), 1e-12f);
    #pragma unroll
    for (int i = 0; i < 4; i++)
        out[(size_t)c * DD + i * 256 + tid] = u[i] * inv;
}

// ---------------- launch ----------------
extern "C" void kernel_launch(void* const* d_in, const int* in_sizes, int n_in,
                              void* d_out, int out_size) {
    const float* w   = (const float*)d_in[0];
    const float* F   = (const float*)d_in[1];
    const float* Et  = (const float*)d_in[2];
    const float* fC  = (const float*)d_in[3];
    const float* W1  = (const float*)d_in[4];
    const float* W2  = (const float*)d_in[5];
    const float* Wv  = (const float*)d_in[6];
    const float* Wf  = (const float*)d_in[7];
    // alpha (d_in[8]) cancels in softmax — unused
    const float* beta = (const float*)d_in[9];
    const float* g1w = (const float*)d_in[10];
    const float* g1b = (const float*)d_in[11];
    const float* g2w = (const float*)d_in[12];
    const float* g2b = (const float*)d_in[13];
    float* out = (float*)d_out;

    __nv_bfloat16 *Wc, *wfm, *QH, *W1t, *Wvb, *g2wb, *qt, *Z;
    float *gbuf, *U;
    cudaGetSymbolAddress((void**)&Wc,   g_Wc);
    cudaGetSymbolAddress((void**)&wfm,  g_wfm);
    cudaGetSymbolAddress((void**)&QH,   g_QH);
    cudaGetSymbolAddress((void**)&W1t,  g_W1t);
    cudaGetSymbolAddress((void**)&Wvb,  g_Wvb);
    cudaGetSymbolAddress((void**)&g2wb, g_g2wb);
    cudaGetSymbolAddress((void**)&qt,   g_qt);
    cudaGetSymbolAddress((void**)&Z,    g_Z);
    cudaGetSymbolAddress((void**)&gbuf, g_g);
    cudaGetSymbolAddress((void**)&U,    g_U);

    cudaFuncSetAttribute(attn_fused_k, cudaFuncAttributeMaxDynamicSharedMemorySize, ATTN_SMEM);

    prep_fat_k<<<PREP_TOTAL / 256, 256>>>(w, Et, fC, W1, W2, Wv, Wf, beta, g1w, g2w,
                                          Wc, wfm, W1t, Wvb, g2wb);
    gemm_qh_k<<<dim3(16, 16), 256>>>(wfm, Wc, QH, g1b);
    gemm_fat_k<<<1280, 256>>>(QH, W1t, qt, g2wb, gbuf, g2b);
    attn_fused_k<<<1024, 1024, ATTN_SMEM>>>(F, Et, qt, Z);
    gemm_gate_k<<<dim3(1, 16, 8), 256>>>(Z, Wvb, U, gbuf, w);
    finalize_k<<<CC, 256>>>(U, out);
}